// round 1
// baseline (speedup 1.0000x reference)
#include <cuda_runtime.h>
#include <math.h>

// Problem constants
#define BB 4
#define TT 2048
#define CC 1024
#define NH 16
#define HSZ 64
// derived
#define MROWS (BB*TT)        // 8192
#define THREECC (3*CC)       // 3072

// Scratch (device globals: allocation-free)
__device__ float g_qkv[(size_t)BB*TT*3*CC];   // 96 MB
__device__ float g_att[(size_t)BB*TT*CC];     // 32 MB

// ---------------------------------------------------------------------------
// SGEMM with bias: C[M,N] = A[M,K] @ B[K,N] + bias[N]
// 128x128 block tile, BK=16, 256 threads, 8x8 microtile.
// M,N,K all divisible by tile dims for this problem (no bounds checks).
// ---------------------------------------------------------------------------
__global__ __launch_bounds__(256) void sgemm_bias(
    int M, int N, int K,
    const float* __restrict__ A,
    const float* __restrict__ Bm,
    const float* __restrict__ bias,
    float* __restrict__ Cm)
{
    constexpr int BM = 128, BN = 128, BK = 16, TM = 8, TN = 8;
    __shared__ float As[BK][BM];
    __shared__ float Bs[BK][BN];

    const int cRow = blockIdx.y;
    const int cCol = blockIdx.x;
    const int tid  = threadIdx.x;

    const int threadCol = tid % (BN / TN);   // 0..15
    const int threadRow = tid / (BN / TN);   // 0..15

    const float* Ap = A + (size_t)cRow * BM * K;
    const float* Bp = Bm + cCol * BN;

    const int innerRowA = tid / (BK / 4);    // 0..63
    const int innerColA = tid % (BK / 4);    // 0..3
    const int innerRowB = tid / (BN / 4);    // 0..7
    const int innerColB = tid % (BN / 4);    // 0..31
    constexpr int strideA = 256 / (BK / 4);  // 64
    constexpr int strideB = 256 / (BN / 4);  // 8

    float acc[TM][TN] = {};
    float regM[TM], regN[TN];

    for (int k0 = 0; k0 < K; k0 += BK) {
        #pragma unroll
        for (int r = 0; r < BM; r += strideA) {
            float4 t = *(const float4*)&Ap[(size_t)(innerRowA + r) * K + innerColA * 4];
            As[innerColA * 4 + 0][innerRowA + r] = t.x;
            As[innerColA * 4 + 1][innerRowA + r] = t.y;
            As[innerColA * 4 + 2][innerRowA + r] = t.z;
            As[innerColA * 4 + 3][innerRowA + r] = t.w;
        }
        #pragma unroll
        for (int r = 0; r < BK; r += strideB) {
            *(float4*)&Bs[innerRowB + r][innerColB * 4] =
                *(const float4*)&Bp[(size_t)(innerRowB + r) * N + innerColB * 4];
        }
        __syncthreads();
        Ap += BK;
        Bp += (size_t)BK * N;

        #pragma unroll
        for (int k = 0; k < BK; k++) {
            #pragma unroll
            for (int i = 0; i < TM; i++) regM[i] = As[k][threadRow * TM + i];
            #pragma unroll
            for (int j = 0; j < TN; j++) regN[j] = Bs[k][threadCol * TN + j];
            #pragma unroll
            for (int i = 0; i < TM; i++)
                #pragma unroll
                for (int j = 0; j < TN; j++)
                    acc[i][j] = fmaf(regM[i], regN[j], acc[i][j]);
        }
        __syncthreads();
    }

    #pragma unroll
    for (int i = 0; i < TM; i++) {
        const int row = cRow * BM + threadRow * TM + i;
        #pragma unroll
        for (int j = 0; j < TN; j += 4) {
            const int col = cCol * BN + threadCol * TN + j;
            float4 bv = *(const float4*)&bias[col];
            float4 o;
            o.x = acc[i][j + 0] + bv.x;
            o.y = acc[i][j + 1] + bv.y;
            o.z = acc[i][j + 2] + bv.z;
            o.w = acc[i][j + 3] + bv.w;
            *(float4*)&Cm[(size_t)row * N + col] = o;
        }
    }
}

// ---------------------------------------------------------------------------
// Flash-style causal attention over g_qkv -> g_att.
// Grid: (T/64, B*H). Block: 256 threads = 8 warps; warp owns 8 query rows.
// Per lane: keys {lane, lane+32} for scores; dims {2*lane, 2*lane+1} for O.
// Smem: Q/K/V tiles 64x64, padded to row stride 68 floats (conflict-free
// LDS.128 across lanes). Dynamic smem = 3*64*68*4 = 52224 B.
// ---------------------------------------------------------------------------
#define ATTN_SMEM_BYTES (3 * 64 * 68 * 4)

__global__ __launch_bounds__(256) void flash_attn_kernel()
{
    extern __shared__ float sm[];
    float* Qs = sm;                 // 64 x 68
    float* Ks = sm + 64 * 68;
    float* Vs = sm + 2 * 64 * 68;

    const int qt = blockIdx.x;          // 0..31
    const int bh = blockIdx.y;          // 0..63
    const int b  = bh / NH;
    const int h  = bh % NH;
    const int tid  = threadIdx.x;
    const int warp = tid >> 5;
    const int lane = tid & 31;
    const int q0 = qt * 64;

    // Load Q tile
    for (int idx = tid; idx < 64 * 16; idx += 256) {
        const int row = idx >> 4, c4 = idx & 15;
        const float4 v = *(const float4*)
            &g_qkv[(size_t)(b * TT + q0 + row) * THREECC + h * HSZ + c4 * 4];
        *(float4*)&Qs[row * 68 + c4 * 4] = v;
    }

    float  m[8], l[8];
    float2 o[8];
    #pragma unroll
    for (int i = 0; i < 8; i++) { m[i] = -1e30f; l[i] = 0.f; o[i] = make_float2(0.f, 0.f); }

    for (int jt = 0; jt <= qt; jt++) {
        const int j0 = jt * 64;
        __syncthreads();  // protect K/V (and on first iter, orders Q fill too)
        for (int idx = tid; idx < 64 * 16; idx += 256) {
            const int row = idx >> 4, c4 = idx & 15;
            const size_t base = (size_t)(b * TT + j0 + row) * THREECC + h * HSZ + c4 * 4;
            *(float4*)&Ks[row * 68 + c4 * 4] = *(const float4*)&g_qkv[base + CC];
            *(float4*)&Vs[row * 68 + c4 * 4] = *(const float4*)&g_qkv[base + 2 * CC];
        }
        __syncthreads();

        const bool diag = (jt == qt);

        #pragma unroll
        for (int rr = 0; rr < 8; rr++) {
            const int r = warp * 8 + rr;

            float s0 = 0.f, s1 = 0.f;
            const float4* q4  = (const float4*)&Qs[r * 68];
            const float4* k4a = (const float4*)&Ks[lane * 68];
            const float4* k4b = (const float4*)&Ks[(lane + 32) * 68];
            #pragma unroll
            for (int d4 = 0; d4 < 16; d4++) {
                const float4 q = q4[d4], ka = k4a[d4], kb = k4b[d4];
                s0 = fmaf(q.x, ka.x, s0); s0 = fmaf(q.y, ka.y, s0);
                s0 = fmaf(q.z, ka.z, s0); s0 = fmaf(q.w, ka.w, s0);
                s1 = fmaf(q.x, kb.x, s1); s1 = fmaf(q.y, kb.y, s1);
                s1 = fmaf(q.z, kb.z, s1); s1 = fmaf(q.w, kb.w, s1);
            }
            s0 *= 0.125f;   // 1/sqrt(64)
            s1 *= 0.125f;
            if (diag) {
                const int qi = q0 + r;
                if (j0 + lane      > qi) s0 = -1e30f;
                if (j0 + lane + 32 > qi) s1 = -1e30f;
            }

            float mt = fmaxf(s0, s1);
            #pragma unroll
            for (int off = 16; off > 0; off >>= 1)
                mt = fmaxf(mt, __shfl_xor_sync(0xffffffffu, mt, off));
            const float mnew = fmaxf(m[rr], mt);

            const float p0 = __expf(s0 - mnew);
            const float p1 = __expf(s1 - mnew);
            float ps = p0 + p1;
            #pragma unroll
            for (int off = 16; off > 0; off >>= 1)
                ps += __shfl_xor_sync(0xffffffffu, ps, off);

            const float alpha = __expf(m[rr] - mnew);
            m[rr] = mnew;
            l[rr] = l[rr] * alpha + ps;
            o[rr].x *= alpha;
            o[rr].y *= alpha;

            #pragma unroll
            for (int kk = 0; kk < 32; kk++) {
                const float pv = __shfl_sync(0xffffffffu, p0, kk);
                const float2 v2 = *(const float2*)&Vs[kk * 68 + 2 * lane];
                o[rr].x = fmaf(pv, v2.x, o[rr].x);
                o[rr].y = fmaf(pv, v2.y, o[rr].y);
            }
            #pragma unroll
            for (int kk = 0; kk < 32; kk++) {
                const float pv = __shfl_sync(0xffffffffu, p1, kk);
                const float2 v2 = *(const float2*)&Vs[(kk + 32) * 68 + 2 * lane];
                o[rr].x = fmaf(pv, v2.x, o[rr].x);
                o[rr].y = fmaf(pv, v2.y, o[rr].y);
            }
        }
    }

    #pragma unroll
    for (int rr = 0; rr < 8; rr++) {
        const int r  = warp * 8 + rr;
        const int qi = q0 + r;
        const float inv = 1.0f / l[rr];
        const float2 out = make_float2(o[rr].x * inv, o[rr].y * inv);
        *(float2*)&g_att[(size_t)(b * TT + qi) * CC + h * HSZ + 2 * lane] = out;
    }
}

// ---------------------------------------------------------------------------
extern "C" void kernel_launch(void* const* d_in, const int* in_sizes, int n_in,
                              void* d_out, int out_size)
{
    const float* x      = (const float*)d_in[0];
    const float* w_attn = (const float*)d_in[1];
    const float* b_attn = (const float*)d_in[2];
    const float* w_proj = (const float*)d_in[3];
    const float* b_proj = (const float*)d_in[4];
    float* out = (float*)d_out;

    float* qkv = nullptr;
    float* att = nullptr;
    cudaGetSymbolAddress((void**)&qkv, g_qkv);
    cudaGetSymbolAddress((void**)&att, g_att);

    cudaFuncSetAttribute(flash_attn_kernel,
                         cudaFuncAttributeMaxDynamicSharedMemorySize,
                         ATTN_SMEM_BYTES);

    // 1) qkv = x @ w_attn + b_attn     [8192,3072]
    sgemm_bias<<<dim3(THREECC / 128, MROWS / 128), 256>>>(
        MROWS, THREECC, CC, x, w_attn, b_attn, qkv);

    // 2) causal flash attention       g_qkv -> g_att [8192,1024]
    flash_attn_kernel<<<dim3(TT / 64, BB * NH), 256, ATTN_SMEM_BYTES>>>();

    // 3) out = att @ w_proj + b_proj  [8192,1024]
    sgemm_bias<<<dim3(CC / 128, MROWS / 128), 256>>>(
        MROWS, CC, CC, att, w_proj, b_proj, out);
}

// round 3
// speedup vs baseline: 1.2582x; 1.2582x over previous
#include <cuda_runtime.h>
#include <cuda_bf16.h>
#include <cstdint>
#include <math.h>

// Problem constants
#define BB 4
#define TT 2048
#define CC 1024
#define NH 16
#define HSZ 64
#define MROWS (BB*TT)        // 8192
#define THREECC (3*CC)       // 3072
#define KD 1024

// ---------------------------------------------------------------------------
// Global scratch (device globals: allocation-free)
// ---------------------------------------------------------------------------
__device__ float g_qkv[(size_t)MROWS * THREECC];          // 96 MB
__device__ float g_att[(size_t)MROWS * CC];               // 32 MB
__device__ __nv_bfloat16 g_xh[(size_t)MROWS * CC];        // x hi/lo  [M][K]
__device__ __nv_bfloat16 g_xl[(size_t)MROWS * CC];
__device__ __nv_bfloat16 g_wah[(size_t)THREECC * CC];     // w_attn^T [N][K]
__device__ __nv_bfloat16 g_wal[(size_t)THREECC * CC];
__device__ __nv_bfloat16 g_wph[(size_t)CC * CC];          // w_proj^T [N][K]
__device__ __nv_bfloat16 g_wpl[(size_t)CC * CC];
__device__ __nv_bfloat16 g_ah[(size_t)MROWS * CC];        // att hi/lo [M][K]
__device__ __nv_bfloat16 g_al[(size_t)MROWS * CC];

// ---------------------------------------------------------------------------
// Helpers (compute_103-safe PTX only: cp.async / ldmatrix / mma.sync)
// ---------------------------------------------------------------------------
__device__ __forceinline__ uint32_t smem_u32(const void* p) {
    uint32_t a;
    asm("{ .reg .u64 t; cvta.to.shared.u64 t, %1; cvt.u32.u64 %0, t; }"
        : "=r"(a) : "l"(p));
    return a;
}

__device__ __forceinline__ void cp16(uint32_t dst, const void* src) {
    asm volatile("cp.async.cg.shared.global [%0], [%1], 16;"
                 :: "r"(dst), "l"(src));
}

__device__ __forceinline__ void ldm_x4(uint32_t* r, uint32_t addr) {
    asm volatile("ldmatrix.sync.aligned.m8n8.x4.shared.b16 {%0,%1,%2,%3}, [%4];"
                 : "=r"(r[0]), "=r"(r[1]), "=r"(r[2]), "=r"(r[3]) : "r"(addr));
}

#define MMA_BF16(acc, a, b0, b1)                                              \
    asm volatile(                                                             \
        "mma.sync.aligned.m16n8k16.row.col.f32.bf16.bf16.f32 "                \
        "{%0,%1,%2,%3},{%4,%5,%6,%7},{%8,%9},{%0,%1,%2,%3};"                  \
        : "+f"((acc)[0]), "+f"((acc)[1]), "+f"((acc)[2]), "+f"((acc)[3])      \
        : "r"((a)[0]), "r"((a)[1]), "r"((a)[2]), "r"((a)[3]),                 \
          "r"(b0), "r"(b1))

__device__ __forceinline__ void split2(float x, uint16_t& h, uint16_t& l) {
    __nv_bfloat16 hb = __float2bfloat16_rn(x);
    float r = x - __bfloat162float(hb);
    __nv_bfloat16 lb = __float2bfloat16_rn(r);
    h = *(uint16_t*)&hb;
    l = *(uint16_t*)&lb;
}

// ---------------------------------------------------------------------------
// fp32 -> bf16 hi/lo planes (same layout)
// ---------------------------------------------------------------------------
__global__ __launch_bounds__(256) void k_split(
    const float4* __restrict__ s, uint2* __restrict__ h, uint2* __restrict__ l, int n4)
{
    const int i = blockIdx.x * 256 + threadIdx.x;
    if (i >= n4) return;
    const float4 v = s[i];
    uint16_t h0, l0, h1, l1, h2, l2, h3, l3;
    split2(v.x, h0, l0); split2(v.y, h1, l1);
    split2(v.z, h2, l2); split2(v.w, h3, l3);
    h[i] = make_uint2((uint32_t)h0 | ((uint32_t)h1 << 16),
                      (uint32_t)h2 | ((uint32_t)h3 << 16));
    l[i] = make_uint2((uint32_t)l0 | ((uint32_t)l1 << 16),
                      (uint32_t)l2 | ((uint32_t)l3 << 16));
}

// fp32 [K][N] -> bf16 hi/lo planes transposed [N][K]
__global__ __launch_bounds__(256) void k_splitT(
    const float* __restrict__ s, __nv_bfloat16* __restrict__ h,
    __nv_bfloat16* __restrict__ l, int K, int N)
{
    __shared__ float t[32][33];
    const int n0 = blockIdx.x * 32, k0 = blockIdx.y * 32;
    const int tx = threadIdx.x, ty = threadIdx.y;   // 32 x 8
    #pragma unroll
    for (int j = ty; j < 32; j += 8)
        t[j][tx] = s[(size_t)(k0 + j) * N + n0 + tx];
    __syncthreads();
    #pragma unroll
    for (int j = ty; j < 32; j += 8) {
        const float v = t[tx][j];
        uint16_t hh, ll;
        split2(v, hh, ll);
        const size_t o = (size_t)(n0 + j) * K + k0 + tx;
        h[o] = *(__nv_bfloat16*)&hh;
        l[o] = *(__nv_bfloat16*)&ll;
    }
}

// ---------------------------------------------------------------------------
// Tensor-core GEMM (mma.sync bf16, 3-term split):
//   C[M][N] = A[M][K] @ Bt[N][K]^T + bias,   K = 1024
// 128x128 CTA tile, BK=32, 256 threads, warp tile 64x32 (2x4 warp grid).
// 4-stage cp.async pipeline. Smem rows: 32 bf16 @ stride 40 elems (80B)
// -> conflict-free ldmatrix (quad = (5*row + chunk) & 7 is a permutation).
// ---------------------------------------------------------------------------
#define STAGE_BYTES (4 * 10240)
#define OFF_AH 0
#define OFF_AL 10240
#define OFF_BH 20480
#define OFF_BL 30720
#define GEMM_SMEM (4 * STAGE_BYTES)   // 163840

__global__ __launch_bounds__(256, 1) void tc_gemm(
    int Ndim,
    const __nv_bfloat16* __restrict__ Ah, const __nv_bfloat16* __restrict__ Al,
    const __nv_bfloat16* __restrict__ Bh, const __nv_bfloat16* __restrict__ Bl,
    const float* __restrict__ bias, float* __restrict__ Cg)
{
    extern __shared__ __align__(128) unsigned char smraw[];
    const uint32_t sb0 = smem_u32(smraw);
    const int tid = threadIdx.x, lane = tid & 31, wid = tid >> 5;
    const int m0 = blockIdx.y * 128, n0 = blockIdx.x * 128;
    const int wm = (wid >> 2) * 64, wn = (wid & 3) * 32;

    // ---- async loader: 8 x 16B per thread per stage
    const int lr = tid >> 2;          // 0..63
    const int lc = tid & 3;           // 16B chunk in a 64B row
    const __nv_bfloat16* gAh = Ah + (size_t)(m0 + lr) * KD + lc * 8;
    const __nv_bfloat16* gAl = Al + (size_t)(m0 + lr) * KD + lc * 8;
    const __nv_bfloat16* gBh = Bh + (size_t)(n0 + lr) * KD + lc * 8;
    const __nv_bfloat16* gBl = Bl + (size_t)(n0 + lr) * KD + lc * 8;
    const uint32_t dOff  = (uint32_t)(lr * 80 + lc * 16);
    const uint32_t dOff2 = dOff + 64 * 80;
    const size_t   gOff2 = (size_t)64 * KD;

    auto issue = [&](int stage, int kc) {
        const int k0 = kc * 32;
        const uint32_t sb = sb0 + stage * STAGE_BYTES;
        cp16(sb + OFF_AH + dOff,  gAh + k0);
        cp16(sb + OFF_AH + dOff2, gAh + k0 + gOff2);
        cp16(sb + OFF_AL + dOff,  gAl + k0);
        cp16(sb + OFF_AL + dOff2, gAl + k0 + gOff2);
        cp16(sb + OFF_BH + dOff,  gBh + k0);
        cp16(sb + OFF_BH + dOff2, gBh + k0 + gOff2);
        cp16(sb + OFF_BL + dOff,  gBl + k0);
        cp16(sb + OFF_BL + dOff2, gBl + k0 + gOff2);
    };

    issue(0, 0); asm volatile("cp.async.commit_group;" ::: "memory");
    issue(1, 1); asm volatile("cp.async.commit_group;" ::: "memory");
    issue(2, 2); asm volatile("cp.async.commit_group;" ::: "memory");

    float acc[4][4][4] = {};

    // ldmatrix per-lane addresses (within a stage)
    const uint32_t aRowOff = (uint32_t)((wm + (lane & 15)) * 80);
    const uint32_t aColHalf = (uint32_t)((lane >> 4) * 16);
    const uint32_t bRowOff = (uint32_t)((wn + (lane >> 4) * 8 + (lane & 7)) * 80);
    const uint32_t bColHalf = (uint32_t)(((lane >> 3) & 1) * 16);

    for (int c = 0; c < 32; c++) {
        asm volatile("cp.async.wait_group 2;" ::: "memory");
        __syncthreads();
        if (c + 3 < 32) issue((c + 3) & 3, c + 3);
        asm volatile("cp.async.commit_group;" ::: "memory");

        const uint32_t sb = sb0 + (c & 3) * STAGE_BYTES;
        #pragma unroll
        for (int ks = 0; ks < 2; ks++) {
            uint32_t ah[4][4], al[4][4], bh[2][4], bl[2][4];
            const uint32_t acol = (uint32_t)(ks * 32) + aColHalf;
            const uint32_t bcol = (uint32_t)(ks * 32) + bColHalf;
            #pragma unroll
            for (int mt = 0; mt < 4; mt++) {
                ldm_x4(ah[mt], sb + OFF_AH + aRowOff + (uint32_t)(mt * 16 * 80) + acol);
                ldm_x4(al[mt], sb + OFF_AL + aRowOff + (uint32_t)(mt * 16 * 80) + acol);
            }
            #pragma unroll
            for (int p = 0; p < 2; p++) {
                ldm_x4(bh[p], sb + OFF_BH + bRowOff + (uint32_t)(p * 16 * 80) + bcol);
                ldm_x4(bl[p], sb + OFF_BL + bRowOff + (uint32_t)(p * 16 * 80) + bcol);
            }
            #pragma unroll
            for (int mt = 0; mt < 4; mt++) {
                #pragma unroll
                for (int nt = 0; nt < 4; nt++) {
                    const uint32_t* bhp = &bh[nt >> 1][(nt & 1) * 2];
                    const uint32_t* blp = &bl[nt >> 1][(nt & 1) * 2];
                    MMA_BF16(acc[mt][nt], ah[mt], bhp[0], bhp[1]);  // hi*hi
                    MMA_BF16(acc[mt][nt], ah[mt], blp[0], blp[1]);  // hi*lo
                    MMA_BF16(acc[mt][nt], al[mt], bhp[0], bhp[1]);  // lo*hi
                }
            }
        }
    }

    // ---- epilogue: direct float2 stores + bias
    const int er = m0 + wm + (lane >> 2);
    const int ec = n0 + wn + (lane & 3) * 2;
    #pragma unroll
    for (int mt = 0; mt < 4; mt++) {
        #pragma unroll
        for (int nt = 0; nt < 4; nt++) {
            const int r = er + mt * 16;
            const int cn = ec + nt * 8;
            const float b0 = bias[cn], b1 = bias[cn + 1];
            float2 v0 = make_float2(acc[mt][nt][0] + b0, acc[mt][nt][1] + b1);
            float2 v1 = make_float2(acc[mt][nt][2] + b0, acc[mt][nt][3] + b1);
            *(float2*)(Cg + (size_t)r * Ndim + cn) = v0;
            *(float2*)(Cg + (size_t)(r + 8) * Ndim + cn) = v1;
        }
    }
}

// ---------------------------------------------------------------------------
// Flash-style causal attention (unchanged — fp32, passed R1)
// ---------------------------------------------------------------------------
#define ATTN_SMEM_BYTES (3 * 64 * 68 * 4)

__global__ __launch_bounds__(256) void flash_attn_kernel()
{
    extern __shared__ float sm[];
    float* Qs = sm;
    float* Ks = sm + 64 * 68;
    float* Vs = sm + 2 * 64 * 68;

    const int qt = blockIdx.x;
    const int bh = blockIdx.y;
    const int b  = bh / NH;
    const int h  = bh % NH;
    const int tid  = threadIdx.x;
    const int warp = tid >> 5;
    const int lane = tid & 31;
    const int q0 = qt * 64;

    for (int idx = tid; idx < 64 * 16; idx += 256) {
        const int row = idx >> 4, c4 = idx & 15;
        const float4 v = *(const float4*)
            &g_qkv[(size_t)(b * TT + q0 + row) * THREECC + h * HSZ + c4 * 4];
        *(float4*)&Qs[row * 68 + c4 * 4] = v;
    }

    float  m[8], l[8];
    float2 o[8];
    #pragma unroll
    for (int i = 0; i < 8; i++) { m[i] = -1e30f; l[i] = 0.f; o[i] = make_float2(0.f, 0.f); }

    for (int jt = 0; jt <= qt; jt++) {
        const int j0 = jt * 64;
        __syncthreads();
        for (int idx = tid; idx < 64 * 16; idx += 256) {
            const int row = idx >> 4, c4 = idx & 15;
            const size_t base = (size_t)(b * TT + j0 + row) * THREECC + h * HSZ + c4 * 4;
            *(float4*)&Ks[row * 68 + c4 * 4] = *(const float4*)&g_qkv[base + CC];
            *(float4*)&Vs[row * 68 + c4 * 4] = *(const float4*)&g_qkv[base + 2 * CC];
        }
        __syncthreads();

        const bool diag = (jt == qt);

        #pragma unroll
        for (int rr = 0; rr < 8; rr++) {
            const int r = warp * 8 + rr;

            float s0 = 0.f, s1 = 0.f;
            const float4* q4  = (const float4*)&Qs[r * 68];
            const float4* k4a = (const float4*)&Ks[lane * 68];
            const float4* k4b = (const float4*)&Ks[(lane + 32) * 68];
            #pragma unroll
            for (int d4 = 0; d4 < 16; d4++) {
                const float4 q = q4[d4], ka = k4a[d4], kb = k4b[d4];
                s0 = fmaf(q.x, ka.x, s0); s0 = fmaf(q.y, ka.y, s0);
                s0 = fmaf(q.z, ka.z, s0); s0 = fmaf(q.w, ka.w, s0);
                s1 = fmaf(q.x, kb.x, s1); s1 = fmaf(q.y, kb.y, s1);
                s1 = fmaf(q.z, kb.z, s1); s1 = fmaf(q.w, kb.w, s1);
            }
            s0 *= 0.125f;
            s1 *= 0.125f;
            if (diag) {
                const int qi = q0 + r;
                if (j0 + lane      > qi) s0 = -1e30f;
                if (j0 + lane + 32 > qi) s1 = -1e30f;
            }

            float mt = fmaxf(s0, s1);
            #pragma unroll
            for (int off = 16; off > 0; off >>= 1)
                mt = fmaxf(mt, __shfl_xor_sync(0xffffffffu, mt, off));
            const float mnew = fmaxf(m[rr], mt);

            const float p0 = __expf(s0 - mnew);
            const float p1 = __expf(s1 - mnew);
            float ps = p0 + p1;
            #pragma unroll
            for (int off = 16; off > 0; off >>= 1)
                ps += __shfl_xor_sync(0xffffffffu, ps, off);

            const float alpha = __expf(m[rr] - mnew);
            m[rr] = mnew;
            l[rr] = l[rr] * alpha + ps;
            o[rr].x *= alpha;
            o[rr].y *= alpha;

            #pragma unroll
            for (int kk = 0; kk < 32; kk++) {
                const float pv = __shfl_sync(0xffffffffu, p0, kk);
                const float2 v2 = *(const float2*)&Vs[kk * 68 + 2 * lane];
                o[rr].x = fmaf(pv, v2.x, o[rr].x);
                o[rr].y = fmaf(pv, v2.y, o[rr].y);
            }
            #pragma unroll
            for (int kk = 0; kk < 32; kk++) {
                const float pv = __shfl_sync(0xffffffffu, p1, kk);
                const float2 v2 = *(const float2*)&Vs[(kk + 32) * 68 + 2 * lane];
                o[rr].x = fmaf(pv, v2.x, o[rr].x);
                o[rr].y = fmaf(pv, v2.y, o[rr].y);
            }
        }
    }

    #pragma unroll
    for (int rr = 0; rr < 8; rr++) {
        const int r  = warp * 8 + rr;
        const int qi = q0 + r;
        const float inv = 1.0f / l[rr];
        const float2 out = make_float2(o[rr].x * inv, o[rr].y * inv);
        *(float2*)&g_att[(size_t)(b * TT + qi) * CC + h * HSZ + 2 * lane] = out;
    }
}

// ---------------------------------------------------------------------------
extern "C" void kernel_launch(void* const* d_in, const int* in_sizes, int n_in,
                              void* d_out, int out_size)
{
    const float* x      = (const float*)d_in[0];
    const float* w_attn = (const float*)d_in[1];
    const float* b_attn = (const float*)d_in[2];
    const float* w_proj = (const float*)d_in[3];
    const float* b_proj = (const float*)d_in[4];
    float* out = (float*)d_out;

    float *qkv, *att;
    __nv_bfloat16 *xh, *xl, *wah, *wal, *wph, *wpl, *ah, *al;
    cudaGetSymbolAddress((void**)&qkv, g_qkv);
    cudaGetSymbolAddress((void**)&att, g_att);
    cudaGetSymbolAddress((void**)&xh, g_xh);
    cudaGetSymbolAddress((void**)&xl, g_xl);
    cudaGetSymbolAddress((void**)&wah, g_wah);
    cudaGetSymbolAddress((void**)&wal, g_wal);
    cudaGetSymbolAddress((void**)&wph, g_wph);
    cudaGetSymbolAddress((void**)&wpl, g_wpl);
    cudaGetSymbolAddress((void**)&ah, g_ah);
    cudaGetSymbolAddress((void**)&al, g_al);

    cudaFuncSetAttribute(tc_gemm,
                         cudaFuncAttributeMaxDynamicSharedMemorySize, GEMM_SMEM);
    cudaFuncSetAttribute(flash_attn_kernel,
                         cudaFuncAttributeMaxDynamicSharedMemorySize, ATTN_SMEM_BYTES);

    // 0) converts: x -> planes; weights -> transposed planes
    {
        const int n4x = MROWS * CC / 4;
        k_split<<<(n4x + 255) / 256, 256>>>((const float4*)x, (uint2*)xh, (uint2*)xl, n4x);
        k_splitT<<<dim3(THREECC / 32, CC / 32), dim3(32, 8)>>>(w_attn, wah, wal, CC, THREECC);
        k_splitT<<<dim3(CC / 32, CC / 32), dim3(32, 8)>>>(w_proj, wph, wpl, CC, CC);
    }

    // 1) qkv = x @ w_attn + b_attn   [8192,3072]
    tc_gemm<<<dim3(THREECC / 128, MROWS / 128), 256, GEMM_SMEM>>>(
        THREECC, xh, xl, wah, wal, b_attn, qkv);

    // 2) causal flash attention      g_qkv -> g_att
    flash_attn_kernel<<<dim3(TT / 64, BB * NH), 256, ATTN_SMEM_BYTES>>>();

    // 2b) split attention output
    {
        const int n4a = MROWS * CC / 4;
        k_split<<<(n4a + 255) / 256, 256>>>((const float4*)att, (uint2*)ah, (uint2*)al, n4a);
    }

    // 3) out = att @ w_proj + b_proj  [8192,1024]
    tc_gemm<<<dim3(CC / 128, MROWS / 128), 256, GEMM_SMEM>>>(
        CC, ah, al, wph, wpl, b_proj, out);
}

// round 4
// speedup vs baseline: 4.1280x; 3.2808x over previous
#include <cuda_runtime.h>
#include <cuda_bf16.h>
#include <cstdint>
#include <math.h>

// Problem constants
#define BB 4
#define TT 2048
#define CC 1024
#define NH 16
#define HSZ 64
#define MROWS (BB*TT)        // 8192
#define THREECC (3*CC)       // 3072
#define KD 1024

// ---------------------------------------------------------------------------
// Global scratch (device globals: allocation-free)
// ---------------------------------------------------------------------------
__device__ __nv_bfloat16 g_qkvh[(size_t)MROWS * THREECC];  // qkv hi plane
__device__ __nv_bfloat16 g_qkvl[(size_t)MROWS * THREECC];  // qkv lo plane
__device__ __nv_bfloat16 g_xh[(size_t)MROWS * CC];         // x planes [M][K]
__device__ __nv_bfloat16 g_xl[(size_t)MROWS * CC];
__device__ __nv_bfloat16 g_wah[(size_t)THREECC * CC];      // w_attn^T [N][K]
__device__ __nv_bfloat16 g_wal[(size_t)THREECC * CC];
__device__ __nv_bfloat16 g_wph[(size_t)CC * CC];           // w_proj^T [N][K]
__device__ __nv_bfloat16 g_wpl[(size_t)CC * CC];
__device__ __nv_bfloat16 g_ah[(size_t)MROWS * CC];         // attn out planes
__device__ __nv_bfloat16 g_al[(size_t)MROWS * CC];

// ---------------------------------------------------------------------------
// Helpers (compute_103-safe PTX: cp.async / ldmatrix / mma.sync)
// ---------------------------------------------------------------------------
__device__ __forceinline__ uint32_t smem_u32(const void* p) {
    uint32_t a;
    asm("{ .reg .u64 t; cvta.to.shared.u64 t, %1; cvt.u32.u64 %0, t; }"
        : "=r"(a) : "l"(p));
    return a;
}

__device__ __forceinline__ void cp16(uint32_t dst, const void* src) {
    asm volatile("cp.async.cg.shared.global [%0], [%1], 16;"
                 :: "r"(dst), "l"(src));
}
#define CP_COMMIT() asm volatile("cp.async.commit_group;" ::: "memory")
#define CP_WAIT(n)  asm volatile("cp.async.wait_group %0;" :: "n"(n) : "memory")

__device__ __forceinline__ void ldm_x4(uint32_t* r, uint32_t addr) {
    asm volatile("ldmatrix.sync.aligned.m8n8.x4.shared.b16 {%0,%1,%2,%3}, [%4];"
                 : "=r"(r[0]), "=r"(r[1]), "=r"(r[2]), "=r"(r[3]) : "r"(addr));
}
__device__ __forceinline__ void ldm_x4t(uint32_t* r, uint32_t addr) {
    asm volatile("ldmatrix.sync.aligned.m8n8.x4.trans.shared.b16 {%0,%1,%2,%3}, [%4];"
                 : "=r"(r[0]), "=r"(r[1]), "=r"(r[2]), "=r"(r[3]) : "r"(addr));
}

#define MMA_BF16(acc, a, b0, b1)                                              \
    asm volatile(                                                             \
        "mma.sync.aligned.m16n8k16.row.col.f32.bf16.bf16.f32 "                \
        "{%0,%1,%2,%3},{%4,%5,%6,%7},{%8,%9},{%0,%1,%2,%3};"                  \
        : "+f"((acc)[0]), "+f"((acc)[1]), "+f"((acc)[2]), "+f"((acc)[3])      \
        : "r"((a)[0]), "r"((a)[1]), "r"((a)[2]), "r"((a)[3]),                 \
          "r"(b0), "r"(b1))

__device__ __forceinline__ float ex2f(float x) {
    float y;
    asm("ex2.approx.f32 %0, %1;" : "=f"(y) : "f"(x));
    return y;
}

__device__ __forceinline__ void split2(float x, uint16_t& h, uint16_t& l) {
    __nv_bfloat16 hb = __float2bfloat16_rn(x);
    float r = x - __bfloat162float(hb);
    __nv_bfloat16 lb = __float2bfloat16_rn(r);
    h = *(uint16_t*)&hb;
    l = *(uint16_t*)&lb;
}

// pack two floats into bf16x2 hi + bf16x2 lo
__device__ __forceinline__ void pack_split(float a, float b, uint32_t& h, uint32_t& l) {
    __nv_bfloat162 hb = __floats2bfloat162_rn(a, b);
    float ra = a - __low2float(hb);
    float rb = b - __high2float(hb);
    __nv_bfloat162 lb = __floats2bfloat162_rn(ra, rb);
    h = *(uint32_t*)&hb;
    l = *(uint32_t*)&lb;
}

// ---------------------------------------------------------------------------
// fp32 -> bf16 hi/lo planes
// ---------------------------------------------------------------------------
__global__ __launch_bounds__(256) void k_split(
    const float4* __restrict__ s, uint2* __restrict__ h, uint2* __restrict__ l, int n4)
{
    const int i = blockIdx.x * 256 + threadIdx.x;
    if (i >= n4) return;
    const float4 v = s[i];
    uint16_t h0, l0, h1, l1, h2, l2, h3, l3;
    split2(v.x, h0, l0); split2(v.y, h1, l1);
    split2(v.z, h2, l2); split2(v.w, h3, l3);
    h[i] = make_uint2((uint32_t)h0 | ((uint32_t)h1 << 16),
                      (uint32_t)h2 | ((uint32_t)h3 << 16));
    l[i] = make_uint2((uint32_t)l0 | ((uint32_t)l1 << 16),
                      (uint32_t)l2 | ((uint32_t)l3 << 16));
}

// fp32 [K][N] -> planes transposed [N][K]
__global__ __launch_bounds__(256) void k_splitT(
    const float* __restrict__ s, __nv_bfloat16* __restrict__ h,
    __nv_bfloat16* __restrict__ l, int K, int N)
{
    __shared__ float t[32][33];
    const int n0 = blockIdx.x * 32, k0 = blockIdx.y * 32;
    const int tx = threadIdx.x, ty = threadIdx.y;
    #pragma unroll
    for (int j = ty; j < 32; j += 8)
        t[j][tx] = s[(size_t)(k0 + j) * N + n0 + tx];
    __syncthreads();
    #pragma unroll
    for (int j = ty; j < 32; j += 8) {
        const float v = t[tx][j];
        uint16_t hh, ll;
        split2(v, hh, ll);
        const size_t o = (size_t)(n0 + j) * K + k0 + tx;
        h[o] = *(__nv_bfloat16*)&hh;
        l[o] = *(__nv_bfloat16*)&ll;
    }
}

// ---------------------------------------------------------------------------
// Tensor-core GEMM (3-term bf16 split): C = A[M][K] @ Bt[N][K]^T + bias
// planes=0: fp32 C ; planes=1: bf16 hi/lo plane outputs
// ---------------------------------------------------------------------------
#define STAGE_BYTES (4 * 10240)
#define OFF_AH 0
#define OFF_AL 10240
#define OFF_BH 20480
#define OFF_BL 30720
#define GEMM_SMEM (4 * STAGE_BYTES)

__global__ __launch_bounds__(256, 1) void tc_gemm(
    int Ndim,
    const __nv_bfloat16* __restrict__ Ah, const __nv_bfloat16* __restrict__ Al,
    const __nv_bfloat16* __restrict__ Bh, const __nv_bfloat16* __restrict__ Bl,
    const float* __restrict__ bias, float* __restrict__ Cf,
    __nv_bfloat16* __restrict__ Ch, __nv_bfloat16* __restrict__ Cl,
    int planes)
{
    extern __shared__ __align__(128) unsigned char smraw[];
    const uint32_t sb0 = smem_u32(smraw);
    const int tid = threadIdx.x, lane = tid & 31, wid = tid >> 5;
    const int m0 = blockIdx.y * 128, n0 = blockIdx.x * 128;
    const int wm = (wid >> 2) * 64, wn = (wid & 3) * 32;

    const int lr = tid >> 2;
    const int lc = tid & 3;
    const __nv_bfloat16* gAh = Ah + (size_t)(m0 + lr) * KD + lc * 8;
    const __nv_bfloat16* gAl = Al + (size_t)(m0 + lr) * KD + lc * 8;
    const __nv_bfloat16* gBh = Bh + (size_t)(n0 + lr) * KD + lc * 8;
    const __nv_bfloat16* gBl = Bl + (size_t)(n0 + lr) * KD + lc * 8;
    const uint32_t dOff  = (uint32_t)(lr * 80 + lc * 16);
    const uint32_t dOff2 = dOff + 64 * 80;
    const size_t   gOff2 = (size_t)64 * KD;

    auto issue = [&](int stage, int kc) {
        const int k0 = kc * 32;
        const uint32_t sb = sb0 + stage * STAGE_BYTES;
        cp16(sb + OFF_AH + dOff,  gAh + k0);
        cp16(sb + OFF_AH + dOff2, gAh + k0 + gOff2);
        cp16(sb + OFF_AL + dOff,  gAl + k0);
        cp16(sb + OFF_AL + dOff2, gAl + k0 + gOff2);
        cp16(sb + OFF_BH + dOff,  gBh + k0);
        cp16(sb + OFF_BH + dOff2, gBh + k0 + gOff2);
        cp16(sb + OFF_BL + dOff,  gBl + k0);
        cp16(sb + OFF_BL + dOff2, gBl + k0 + gOff2);
    };

    issue(0, 0); CP_COMMIT();
    issue(1, 1); CP_COMMIT();
    issue(2, 2); CP_COMMIT();

    float acc[4][4][4] = {};

    const uint32_t aRowOff  = (uint32_t)((wm + (lane & 15)) * 80);
    const uint32_t aColHalf = (uint32_t)((lane >> 4) * 16);
    const uint32_t bRowOff  = (uint32_t)((wn + (lane >> 4) * 8 + (lane & 7)) * 80);
    const uint32_t bColHalf = (uint32_t)(((lane >> 3) & 1) * 16);

    for (int c = 0; c < 32; c++) {
        CP_WAIT(2);
        __syncthreads();
        if (c + 3 < 32) issue((c + 3) & 3, c + 3);
        CP_COMMIT();

        const uint32_t sb = sb0 + (c & 3) * STAGE_BYTES;
        #pragma unroll
        for (int ks = 0; ks < 2; ks++) {
            uint32_t ah[4][4], al[4][4], bh[2][4], bl[2][4];
            const uint32_t acol = (uint32_t)(ks * 32) + aColHalf;
            const uint32_t bcol = (uint32_t)(ks * 32) + bColHalf;
            #pragma unroll
            for (int mt = 0; mt < 4; mt++) {
                ldm_x4(ah[mt], sb + OFF_AH + aRowOff + (uint32_t)(mt * 16 * 80) + acol);
                ldm_x4(al[mt], sb + OFF_AL + aRowOff + (uint32_t)(mt * 16 * 80) + acol);
            }
            #pragma unroll
            for (int p = 0; p < 2; p++) {
                ldm_x4(bh[p], sb + OFF_BH + bRowOff + (uint32_t)(p * 16 * 80) + bcol);
                ldm_x4(bl[p], sb + OFF_BL + bRowOff + (uint32_t)(p * 16 * 80) + bcol);
            }
            #pragma unroll
            for (int mt = 0; mt < 4; mt++) {
                #pragma unroll
                for (int nt = 0; nt < 4; nt++) {
                    const uint32_t* bhp = &bh[nt >> 1][(nt & 1) * 2];
                    const uint32_t* blp = &bl[nt >> 1][(nt & 1) * 2];
                    MMA_BF16(acc[mt][nt], ah[mt], bhp[0], bhp[1]);
                    MMA_BF16(acc[mt][nt], ah[mt], blp[0], blp[1]);
                    MMA_BF16(acc[mt][nt], al[mt], bhp[0], bhp[1]);
                }
            }
        }
    }

    const int er = m0 + wm + (lane >> 2);
    const int ec = n0 + wn + (lane & 3) * 2;
    #pragma unroll
    for (int mt = 0; mt < 4; mt++) {
        #pragma unroll
        for (int nt = 0; nt < 4; nt++) {
            const int r = er + mt * 16;
            const int cn = ec + nt * 8;
            const float b0 = bias[cn], b1 = bias[cn + 1];
            const float v0 = acc[mt][nt][0] + b0, v1 = acc[mt][nt][1] + b1;
            const float v2 = acc[mt][nt][2] + b0, v3 = acc[mt][nt][3] + b1;
            if (!planes) {
                *(float2*)(Cf + (size_t)r * Ndim + cn) = make_float2(v0, v1);
                *(float2*)(Cf + (size_t)(r + 8) * Ndim + cn) = make_float2(v2, v3);
            } else {
                uint32_t hh, ll;
                pack_split(v0, v1, hh, ll);
                *(uint32_t*)(Ch + (size_t)r * Ndim + cn) = hh;
                *(uint32_t*)(Cl + (size_t)r * Ndim + cn) = ll;
                pack_split(v2, v3, hh, ll);
                *(uint32_t*)(Ch + (size_t)(r + 8) * Ndim + cn) = hh;
                *(uint32_t*)(Cl + (size_t)(r + 8) * Ndim + cn) = ll;
            }
        }
    }
}

// ---------------------------------------------------------------------------
// Tensor-core causal flash attention.
// CTA = 128 queries x one (b,h). 8 warps x 16 rows. K-tile = 64 keys.
// Q/K/V consumed as bf16 hi/lo planes (from GEMM1); 3-term split products.
// Output written as bf16 hi/lo planes for GEMM2.
// Smem: Q planes 2x128x144B = 36864; K/V 2 stages x 4 planes x 64x144B = 73728.
// Row stride 144B -> (9*row + chunk16) % 8 is a permutation: ldmatrix
// and cp.async conflict-free.
// ---------------------------------------------------------------------------
#define FLASH_SMEM (36864 + 73728)

__global__ __launch_bounds__(256) void flash_tc()
{
    extern __shared__ __align__(128) unsigned char fsm[];
    const uint32_t sm0 = smem_u32(fsm);
    const int tid = threadIdx.x, lane = tid & 31, wid = tid >> 5;
    const int qt = blockIdx.x;
    const int b = blockIdx.y >> 4, h = blockIdx.y & 15;
    const int q0 = qt * 128, wm = wid * 16;
    const size_t rowB = (size_t)b * TT;
    const int h64 = h * 64;
    const int NT = 2 * qt + 2;

    const uint32_t OQ = sm0, OKV = sm0 + 36864;

    auto issueQ = [&]() {
        #pragma unroll
        for (int j = 0; j < 8; j++) {
            const int c = j * 256 + tid;
            const int pl = c >> 10, row = (c >> 3) & 127, ch = c & 7;
            const __nv_bfloat16* src = (pl ? g_qkvl : g_qkvh)
                + (rowB + q0 + row) * THREECC + h64 + ch * 8;
            cp16(OQ + pl * 18432 + row * 144 + ch * 16, src);
        }
    };
    auto issueKV = [&](int st, int tt) {
        const int j0 = tt * 64;
        const uint32_t sb = OKV + st * 36864;
        #pragma unroll
        for (int j = 0; j < 8; j++) {
            const int c = j * 256 + tid;
            const int pl = c >> 9, row = (c >> 3) & 63, ch = c & 7;
            const __nv_bfloat16* src = ((pl & 1) ? g_qkvl : g_qkvh)
                + (rowB + j0 + row) * THREECC + ((pl >> 1) ? 2 * CC : CC) + h64 + ch * 8;
            cp16(sb + pl * 9216 + row * 144 + ch * 16, src);
        }
    };

    issueQ(); CP_COMMIT();
    issueKV(0, 0); CP_COMMIT();
    if (NT > 1) issueKV(1, 1);
    CP_COMMIT();

    // lane-derived ldmatrix offsets
    const uint32_t koff = (uint32_t)(((((lane >> 4) & 1) * 8 + (lane & 7)) * 144)
                                     + ((lane >> 3) & 1) * 16);
    const uint32_t voff = (uint32_t)(((((lane >> 3) & 1) * 8 + (lane & 7)) * 144)
                                     + ((lane >> 4) & 1) * 16);
    const uint32_t qoff = (uint32_t)(((wm + ((lane >> 3) & 1) * 8 + (lane & 7)) * 144)
                                     + ((lane >> 4) & 1) * 16);

    // wait Q group (2 KV groups may stay pending), then load Q fragments
    CP_WAIT(2);
    __syncthreads();
    uint32_t qhf[4][4], qlf[4][4];
    #pragma unroll
    for (int ks = 0; ks < 4; ks++) {
        ldm_x4(qhf[ks], OQ + qoff + ks * 32);
        ldm_x4(qlf[ks], OQ + 18432 + qoff + ks * 32);
    }

    float m0r = -1e30f, m1r = -1e30f, l0r = 0.f, l1r = 0.f;
    float o[8][4] = {};
    const float SC = 0.125f * 1.4426950408889634f;   // scale * log2(e)
    const int rq0 = q0 + wm + (lane >> 2);           // global row (c0/c1)
    const int colb = (lane & 3) * 2;

    for (int t = 0; t < NT; t++) {
        CP_WAIT(1);
        __syncthreads();
        const uint32_t sb  = OKV + (t & 1) * 36864;
        const uint32_t KH = sb, KL = sb + 9216, VH = sb + 18432, VL = sb + 27648;
        const int j0 = t * 64;

        // ---- S = (Q hi/lo) . (K hi/lo)^T, 3 terms
        float s[8][4] = {};
        #pragma unroll
        for (int ks = 0; ks < 4; ks++) {
            uint32_t kh[4][4], kl[4][4];
            #pragma unroll
            for (int g = 0; g < 4; g++) {
                ldm_x4(kh[g], KH + g * 2304 + ks * 32 + koff);
                ldm_x4(kl[g], KL + g * 2304 + ks * 32 + koff);
            }
            #pragma unroll
            for (int g = 0; g < 4; g++) {
                MMA_BF16(s[2*g],   qhf[ks], kh[g][0], kh[g][1]);
                MMA_BF16(s[2*g],   qhf[ks], kl[g][0], kl[g][1]);
                MMA_BF16(s[2*g],   qlf[ks], kh[g][0], kh[g][1]);
                MMA_BF16(s[2*g+1], qhf[ks], kh[g][2], kh[g][3]);
                MMA_BF16(s[2*g+1], qhf[ks], kl[g][2], kl[g][3]);
                MMA_BF16(s[2*g+1], qlf[ks], kh[g][2], kh[g][3]);
            }
        }

        // ---- scale (+ causal mask on diagonal tiles)
        if (t >= 2 * qt) {
            #pragma unroll
            for (int nt = 0; nt < 8; nt++) {
                const int c0 = j0 + nt * 8 + colb;
                #pragma unroll
                for (int j = 0; j < 4; j++) {
                    const int cg = c0 + (j & 1);
                    const int rg = rq0 + ((j >> 1) << 3);
                    s[nt][j] = (cg <= rg) ? s[nt][j] * SC : -1e30f;
                }
            }
        } else {
            #pragma unroll
            for (int nt = 0; nt < 8; nt++)
                #pragma unroll
                for (int j = 0; j < 4; j++) s[nt][j] *= SC;
        }

        // ---- online softmax (rows r and r+8 per lane)
        float mx0 = -1e30f, mx1 = -1e30f;
        #pragma unroll
        for (int nt = 0; nt < 8; nt++) {
            mx0 = fmaxf(mx0, fmaxf(s[nt][0], s[nt][1]));
            mx1 = fmaxf(mx1, fmaxf(s[nt][2], s[nt][3]));
        }
        mx0 = fmaxf(mx0, __shfl_xor_sync(0xffffffffu, mx0, 1));
        mx0 = fmaxf(mx0, __shfl_xor_sync(0xffffffffu, mx0, 2));
        mx1 = fmaxf(mx1, __shfl_xor_sync(0xffffffffu, mx1, 1));
        mx1 = fmaxf(mx1, __shfl_xor_sync(0xffffffffu, mx1, 2));
        const float mn0 = fmaxf(m0r, mx0), mn1 = fmaxf(m1r, mx1);
        const float a0 = ex2f(m0r - mn0), a1 = ex2f(m1r - mn1);
        m0r = mn0; m1r = mn1;

        float rs0 = 0.f, rs1 = 0.f;
        #pragma unroll
        for (int nt = 0; nt < 8; nt++) {
            s[nt][0] = ex2f(s[nt][0] - mn0);
            s[nt][1] = ex2f(s[nt][1] - mn0);
            s[nt][2] = ex2f(s[nt][2] - mn1);
            s[nt][3] = ex2f(s[nt][3] - mn1);
            rs0 += s[nt][0] + s[nt][1];
            rs1 += s[nt][2] + s[nt][3];
        }
        rs0 += __shfl_xor_sync(0xffffffffu, rs0, 1);
        rs0 += __shfl_xor_sync(0xffffffffu, rs0, 2);
        rs1 += __shfl_xor_sync(0xffffffffu, rs1, 1);
        rs1 += __shfl_xor_sync(0xffffffffu, rs1, 2);
        l0r = l0r * a0 + rs0;
        l1r = l1r * a1 + rs1;

        #pragma unroll
        for (int nt = 0; nt < 8; nt++) {
            o[nt][0] *= a0; o[nt][1] *= a0;
            o[nt][2] *= a1; o[nt][3] *= a1;
        }

        // ---- repack P (S-frag -> A-frag) with hi/lo split
        uint32_t ph[4][4], plo[4][4];
        #pragma unroll
        for (int kt = 0; kt < 4; kt++) {
            pack_split(s[2*kt][0],   s[2*kt][1],   ph[kt][0], plo[kt][0]);
            pack_split(s[2*kt][2],   s[2*kt][3],   ph[kt][1], plo[kt][1]);
            pack_split(s[2*kt+1][0], s[2*kt+1][1], ph[kt][2], plo[kt][2]);
            pack_split(s[2*kt+1][2], s[2*kt+1][3], ph[kt][3], plo[kt][3]);
        }

        // ---- O += P . V, 3 terms
        #pragma unroll
        for (int kt = 0; kt < 4; kt++) {
            uint32_t vh[4][4], vl[4][4];
            #pragma unroll
            for (int g = 0; g < 4; g++) {
                ldm_x4t(vh[g], VH + kt * 2304 + g * 32 + voff);
                ldm_x4t(vl[g], VL + kt * 2304 + g * 32 + voff);
            }
            #pragma unroll
            for (int g = 0; g < 4; g++) {
                MMA_BF16(o[2*g],   ph[kt],  vh[g][0], vh[g][1]);
                MMA_BF16(o[2*g],   ph[kt],  vl[g][0], vl[g][1]);
                MMA_BF16(o[2*g],   plo[kt], vh[g][0], vh[g][1]);
                MMA_BF16(o[2*g+1], ph[kt],  vh[g][2], vh[g][3]);
                MMA_BF16(o[2*g+1], ph[kt],  vl[g][2], vl[g][3]);
                MMA_BF16(o[2*g+1], plo[kt], vh[g][2], vh[g][3]);
            }
        }

        __syncthreads();
        if (t + 2 < NT) issueKV((t + 2) & 1, t + 2);
        CP_COMMIT();
    }

    // ---- epilogue: normalize, split, store hi/lo planes
    const float i0 = 1.0f / l0r, i1 = 1.0f / l1r;
    const size_t r0 = rowB + (size_t)rq0;
    #pragma unroll
    for (int nt = 0; nt < 8; nt++) {
        const int col = h64 + nt * 8 + colb;
        uint32_t hh, ll;
        pack_split(o[nt][0] * i0, o[nt][1] * i0, hh, ll);
        *(uint32_t*)(g_ah + r0 * CC + col) = hh;
        *(uint32_t*)(g_al + r0 * CC + col) = ll;
        pack_split(o[nt][2] * i1, o[nt][3] * i1, hh, ll);
        *(uint32_t*)(g_ah + (r0 + 8) * CC + col) = hh;
        *(uint32_t*)(g_al + (r0 + 8) * CC + col) = ll;
    }
}

// ---------------------------------------------------------------------------
extern "C" void kernel_launch(void* const* d_in, const int* in_sizes, int n_in,
                              void* d_out, int out_size)
{
    const float* x      = (const float*)d_in[0];
    const float* w_attn = (const float*)d_in[1];
    const float* b_attn = (const float*)d_in[2];
    const float* w_proj = (const float*)d_in[3];
    const float* b_proj = (const float*)d_in[4];
    float* out = (float*)d_out;

    __nv_bfloat16 *qkvh, *qkvl, *xh, *xl, *wah, *wal, *wph, *wpl, *ah, *al;
    cudaGetSymbolAddress((void**)&qkvh, g_qkvh);
    cudaGetSymbolAddress((void**)&qkvl, g_qkvl);
    cudaGetSymbolAddress((void**)&xh, g_xh);
    cudaGetSymbolAddress((void**)&xl, g_xl);
    cudaGetSymbolAddress((void**)&wah, g_wah);
    cudaGetSymbolAddress((void**)&wal, g_wal);
    cudaGetSymbolAddress((void**)&wph, g_wph);
    cudaGetSymbolAddress((void**)&wpl, g_wpl);
    cudaGetSymbolAddress((void**)&ah, g_ah);
    cudaGetSymbolAddress((void**)&al, g_al);

    cudaFuncSetAttribute(tc_gemm,
                         cudaFuncAttributeMaxDynamicSharedMemorySize, GEMM_SMEM);
    cudaFuncSetAttribute(flash_tc,
                         cudaFuncAttributeMaxDynamicSharedMemorySize, FLASH_SMEM);

    // 0) input conversions
    {
        const int n4x = MROWS * CC / 4;
        k_split<<<(n4x + 255) / 256, 256>>>((const float4*)x, (uint2*)xh, (uint2*)xl, n4x);
        k_splitT<<<dim3(THREECC / 32, CC / 32), dim3(32, 8)>>>(w_attn, wah, wal, CC, THREECC);
        k_splitT<<<dim3(CC / 32, CC / 32), dim3(32, 8)>>>(w_proj, wph, wpl, CC, CC);
    }

    // 1) qkv planes = split(x @ w_attn + b_attn)
    tc_gemm<<<dim3(THREECC / 128, MROWS / 128), 256, GEMM_SMEM>>>(
        THREECC, xh, xl, wah, wal, b_attn, nullptr, qkvh, qkvl, 1);

    // 2) tensor-core causal flash attention -> g_ah/g_al planes
    flash_tc<<<dim3(TT / 128, BB * NH), 256, FLASH_SMEM>>>();

    // 3) out = att @ w_proj + b_proj (fp32)
    tc_gemm<<<dim3(CC / 128, MROWS / 128), 256, GEMM_SMEM>>>(
        CC, ah, al, wph, wpl, b_proj, out, nullptr, nullptr, 0);
}

// round 5
// speedup vs baseline: 4.5274x; 1.0968x over previous
#include <cuda_runtime.h>
#include <cuda_bf16.h>
#include <cstdint>
#include <math.h>

// Problem constants
#define BB 4
#define TT 2048
#define CC 1024
#define NH 16
#define HSZ 64
#define MROWS (BB*TT)        // 8192
#define THREECC (3*CC)       // 3072
#define KD 1024

// ---------------------------------------------------------------------------
// Global scratch (device globals: allocation-free)
// ---------------------------------------------------------------------------
__device__ __nv_bfloat16 g_qkvh[(size_t)MROWS * THREECC];  // qkv hi plane
__device__ __nv_bfloat16 g_qkvl[(size_t)MROWS * THREECC];  // qkv lo plane
__device__ __nv_bfloat16 g_xh[(size_t)MROWS * CC];         // x planes [M][K]
__device__ __nv_bfloat16 g_xl[(size_t)MROWS * CC];
__device__ __nv_bfloat16 g_wah[(size_t)THREECC * CC];      // w_attn^T [N][K]
__device__ __nv_bfloat16 g_wal[(size_t)THREECC * CC];
__device__ __nv_bfloat16 g_wph[(size_t)CC * CC];           // w_proj^T [N][K]
__device__ __nv_bfloat16 g_wpl[(size_t)CC * CC];
__device__ __nv_bfloat16 g_ah[(size_t)MROWS * CC];         // attn out planes
__device__ __nv_bfloat16 g_al[(size_t)MROWS * CC];

// ---------------------------------------------------------------------------
// Helpers (compute_103-safe PTX: cp.async / ldmatrix / mma.sync)
// ---------------------------------------------------------------------------
__device__ __forceinline__ uint32_t smem_u32(const void* p) {
    uint32_t a;
    asm("{ .reg .u64 t; cvta.to.shared.u64 t, %1; cvt.u32.u64 %0, t; }"
        : "=r"(a) : "l"(p));
    return a;
}

__device__ __forceinline__ void cp16(uint32_t dst, const void* src) {
    asm volatile("cp.async.cg.shared.global [%0], [%1], 16;"
                 :: "r"(dst), "l"(src));
}
#define CP_COMMIT() asm volatile("cp.async.commit_group;" ::: "memory")
#define CP_WAIT(n)  asm volatile("cp.async.wait_group %0;" :: "n"(n) : "memory")

__device__ __forceinline__ void ldm_x4(uint32_t* r, uint32_t addr) {
    asm volatile("ldmatrix.sync.aligned.m8n8.x4.shared.b16 {%0,%1,%2,%3}, [%4];"
                 : "=r"(r[0]), "=r"(r[1]), "=r"(r[2]), "=r"(r[3]) : "r"(addr));
}
__device__ __forceinline__ void ldm_x4t(uint32_t* r, uint32_t addr) {
    asm volatile("ldmatrix.sync.aligned.m8n8.x4.trans.shared.b16 {%0,%1,%2,%3}, [%4];"
                 : "=r"(r[0]), "=r"(r[1]), "=r"(r[2]), "=r"(r[3]) : "r"(addr));
}

#define MMA_BF16(acc, a, b0, b1)                                              \
    asm volatile(                                                             \
        "mma.sync.aligned.m16n8k16.row.col.f32.bf16.bf16.f32 "                \
        "{%0,%1,%2,%3},{%4,%5,%6,%7},{%8,%9},{%0,%1,%2,%3};"                  \
        : "+f"((acc)[0]), "+f"((acc)[1]), "+f"((acc)[2]), "+f"((acc)[3])      \
        : "r"((a)[0]), "r"((a)[1]), "r"((a)[2]), "r"((a)[3]),                 \
          "r"(b0), "r"(b1))

__device__ __forceinline__ float ex2f(float x) {
    float y;
    asm("ex2.approx.f32 %0, %1;" : "=f"(y) : "f"(x));
    return y;
}

__device__ __forceinline__ void split2(float x, uint16_t& h, uint16_t& l) {
    __nv_bfloat16 hb = __float2bfloat16_rn(x);
    float r = x - __bfloat162float(hb);
    __nv_bfloat16 lb = __float2bfloat16_rn(r);
    h = *(uint16_t*)&hb;
    l = *(uint16_t*)&lb;
}

__device__ __forceinline__ void pack_split(float a, float b, uint32_t& h, uint32_t& l) {
    __nv_bfloat162 hb = __floats2bfloat162_rn(a, b);
    float ra = a - __low2float(hb);
    float rb = b - __high2float(hb);
    __nv_bfloat162 lb = __floats2bfloat162_rn(ra, rb);
    h = *(uint32_t*)&hb;
    l = *(uint32_t*)&lb;
}

// ---------------------------------------------------------------------------
// fp32 -> bf16 hi/lo planes
// ---------------------------------------------------------------------------
__global__ __launch_bounds__(256) void k_split(
    const float4* __restrict__ s, uint2* __restrict__ h, uint2* __restrict__ l, int n4)
{
    const int i = blockIdx.x * 256 + threadIdx.x;
    if (i >= n4) return;
    const float4 v = s[i];
    uint16_t h0, l0, h1, l1, h2, l2, h3, l3;
    split2(v.x, h0, l0); split2(v.y, h1, l1);
    split2(v.z, h2, l2); split2(v.w, h3, l3);
    h[i] = make_uint2((uint32_t)h0 | ((uint32_t)h1 << 16),
                      (uint32_t)h2 | ((uint32_t)h3 << 16));
    l[i] = make_uint2((uint32_t)l0 | ((uint32_t)l1 << 16),
                      (uint32_t)l2 | ((uint32_t)l3 << 16));
}

// fp32 [K][N] -> planes transposed [N][K]
__global__ __launch_bounds__(256) void k_splitT(
    const float* __restrict__ s, __nv_bfloat16* __restrict__ h,
    __nv_bfloat16* __restrict__ l, int K, int N)
{
    __shared__ float t[32][33];
    const int n0 = blockIdx.x * 32, k0 = blockIdx.y * 32;
    const int tx = threadIdx.x, ty = threadIdx.y;
    #pragma unroll
    for (int j = ty; j < 32; j += 8)
        t[j][tx] = s[(size_t)(k0 + j) * N + n0 + tx];
    __syncthreads();
    #pragma unroll
    for (int j = ty; j < 32; j += 8) {
        const float v = t[tx][j];
        uint16_t hh, ll;
        split2(v, hh, ll);
        const size_t o = (size_t)(n0 + j) * K + k0 + tx;
        h[o] = *(__nv_bfloat16*)&hh;
        l[o] = *(__nv_bfloat16*)&ll;
    }
}

// ---------------------------------------------------------------------------
// Tensor-core GEMM (3-term bf16 split): C = A[M][K] @ Bt[N][K]^T + bias
// 128x128 CTA tile, BK=32, 256 thr, warp tile 64x32.
// 2-stage cp.async pipeline, 80KB smem -> 2 CTAs/SM (regs capped to 128).
// Term-interleaved MMA emission (same acc touched every 16 MMAs).
// ---------------------------------------------------------------------------
#define STAGE_BYTES (4 * 10240)
#define OFF_AH 0
#define OFF_AL 10240
#define OFF_BH 20480
#define OFF_BL 30720
#define GEMM_SMEM (2 * STAGE_BYTES)   // 81920

__global__ __launch_bounds__(256, 2) void tc_gemm(
    int Ndim,
    const __nv_bfloat16* __restrict__ Ah, const __nv_bfloat16* __restrict__ Al,
    const __nv_bfloat16* __restrict__ Bh, const __nv_bfloat16* __restrict__ Bl,
    const float* __restrict__ bias, float* __restrict__ Cf,
    __nv_bfloat16* __restrict__ Ch, __nv_bfloat16* __restrict__ Cl,
    int planes)
{
    extern __shared__ __align__(128) unsigned char smraw[];
    const uint32_t sb0 = smem_u32(smraw);
    const int tid = threadIdx.x, lane = tid & 31, wid = tid >> 5;
    const int m0 = blockIdx.y * 128, n0 = blockIdx.x * 128;
    const int wm = (wid >> 2) * 64, wn = (wid & 3) * 32;

    const int lr = tid >> 2;
    const int lc = tid & 3;
    const __nv_bfloat16* gAh = Ah + (size_t)(m0 + lr) * KD + lc * 8;
    const __nv_bfloat16* gAl = Al + (size_t)(m0 + lr) * KD + lc * 8;
    const __nv_bfloat16* gBh = Bh + (size_t)(n0 + lr) * KD + lc * 8;
    const __nv_bfloat16* gBl = Bl + (size_t)(n0 + lr) * KD + lc * 8;
    const uint32_t dOff  = (uint32_t)(lr * 80 + lc * 16);
    const uint32_t dOff2 = dOff + 64 * 80;
    const size_t   gOff2 = (size_t)64 * KD;

    auto issue = [&](int stage, int kc) {
        const int k0 = kc * 32;
        const uint32_t sb = sb0 + stage * STAGE_BYTES;
        cp16(sb + OFF_AH + dOff,  gAh + k0);
        cp16(sb + OFF_AH + dOff2, gAh + k0 + gOff2);
        cp16(sb + OFF_AL + dOff,  gAl + k0);
        cp16(sb + OFF_AL + dOff2, gAl + k0 + gOff2);
        cp16(sb + OFF_BH + dOff,  gBh + k0);
        cp16(sb + OFF_BH + dOff2, gBh + k0 + gOff2);
        cp16(sb + OFF_BL + dOff,  gBl + k0);
        cp16(sb + OFF_BL + dOff2, gBl + k0 + gOff2);
    };

    issue(0, 0); CP_COMMIT();
    issue(1, 1); CP_COMMIT();

    float acc[4][4][4] = {};

    const uint32_t aRowOff  = (uint32_t)((wm + (lane & 15)) * 80);
    const uint32_t aColHalf = (uint32_t)((lane >> 4) * 16);
    const uint32_t bRowOff  = (uint32_t)((wn + (lane >> 4) * 8 + (lane & 7)) * 80);
    const uint32_t bColHalf = (uint32_t)(((lane >> 3) & 1) * 16);

    for (int c = 0; c < 32; c++) {
        CP_WAIT(1);
        __syncthreads();

        const uint32_t sb = sb0 + (c & 1) * STAGE_BYTES;
        #pragma unroll
        for (int ks = 0; ks < 2; ks++) {
            uint32_t ah[4][4], al[4][4], bh[2][4], bl[2][4];
            const uint32_t acol = (uint32_t)(ks * 32) + aColHalf;
            const uint32_t bcol = (uint32_t)(ks * 32) + bColHalf;
            #pragma unroll
            for (int mt = 0; mt < 4; mt++) {
                ldm_x4(ah[mt], sb + OFF_AH + aRowOff + (uint32_t)(mt * 16 * 80) + acol);
                ldm_x4(al[mt], sb + OFF_AL + aRowOff + (uint32_t)(mt * 16 * 80) + acol);
            }
            #pragma unroll
            for (int p = 0; p < 2; p++) {
                ldm_x4(bh[p], sb + OFF_BH + bRowOff + (uint32_t)(p * 16 * 80) + bcol);
                ldm_x4(bl[p], sb + OFF_BL + bRowOff + (uint32_t)(p * 16 * 80) + bcol);
            }
            // term-interleaved: each acc touched once per phase
            #pragma unroll
            for (int mt = 0; mt < 4; mt++)
                #pragma unroll
                for (int nt = 0; nt < 4; nt++) {
                    const uint32_t* bp = &bh[nt >> 1][(nt & 1) * 2];
                    MMA_BF16(acc[mt][nt], ah[mt], bp[0], bp[1]);   // hi*hi
                }
            #pragma unroll
            for (int mt = 0; mt < 4; mt++)
                #pragma unroll
                for (int nt = 0; nt < 4; nt++) {
                    const uint32_t* bp = &bl[nt >> 1][(nt & 1) * 2];
                    MMA_BF16(acc[mt][nt], ah[mt], bp[0], bp[1]);   // hi*lo
                }
            #pragma unroll
            for (int mt = 0; mt < 4; mt++)
                #pragma unroll
                for (int nt = 0; nt < 4; nt++) {
                    const uint32_t* bp = &bh[nt >> 1][(nt & 1) * 2];
                    MMA_BF16(acc[mt][nt], al[mt], bp[0], bp[1]);   // lo*hi
                }
        }
        __syncthreads();
        if (c + 2 < 32) issue(c & 1, c + 2);
        CP_COMMIT();
    }

    const int er = m0 + wm + (lane >> 2);
    const int ec = n0 + wn + (lane & 3) * 2;
    #pragma unroll
    for (int mt = 0; mt < 4; mt++) {
        #pragma unroll
        for (int nt = 0; nt < 4; nt++) {
            const int r = er + mt * 16;
            const int cn = ec + nt * 8;
            const float b0 = bias[cn], b1 = bias[cn + 1];
            const float v0 = acc[mt][nt][0] + b0, v1 = acc[mt][nt][1] + b1;
            const float v2 = acc[mt][nt][2] + b0, v3 = acc[mt][nt][3] + b1;
            if (!planes) {
                *(float2*)(Cf + (size_t)r * Ndim + cn) = make_float2(v0, v1);
                *(float2*)(Cf + (size_t)(r + 8) * Ndim + cn) = make_float2(v2, v3);
            } else {
                uint32_t hh, ll;
                pack_split(v0, v1, hh, ll);
                *(uint32_t*)(Ch + (size_t)r * Ndim + cn) = hh;
                *(uint32_t*)(Cl + (size_t)r * Ndim + cn) = ll;
                pack_split(v2, v3, hh, ll);
                *(uint32_t*)(Ch + (size_t)(r + 8) * Ndim + cn) = hh;
                *(uint32_t*)(Cl + (size_t)(r + 8) * Ndim + cn) = ll;
            }
        }
    }
}

// ---------------------------------------------------------------------------
// Tensor-core causal flash attention (heavy-CTA-first, term-interleaved).
// ---------------------------------------------------------------------------
#define FLASH_SMEM (36864 + 73728)

__global__ __launch_bounds__(256) void flash_tc()
{
    extern __shared__ __align__(128) unsigned char fsm[];
    const uint32_t sm0 = smem_u32(fsm);
    const int tid = threadIdx.x, lane = tid & 31, wid = tid >> 5;
    const int qt = (int)(gridDim.x - 1 - blockIdx.x);   // heavy CTAs first
    const int b = blockIdx.y >> 4, h = blockIdx.y & 15;
    const int q0 = qt * 128, wm = wid * 16;
    const size_t rowB = (size_t)b * TT;
    const int h64 = h * 64;
    const int NT = 2 * qt + 2;

    const uint32_t OQ = sm0, OKV = sm0 + 36864;

    auto issueQ = [&]() {
        #pragma unroll
        for (int j = 0; j < 8; j++) {
            const int c = j * 256 + tid;
            const int pl = c >> 10, row = (c >> 3) & 127, ch = c & 7;
            const __nv_bfloat16* src = (pl ? g_qkvl : g_qkvh)
                + (rowB + q0 + row) * THREECC + h64 + ch * 8;
            cp16(OQ + pl * 18432 + row * 144 + ch * 16, src);
        }
    };
    auto issueKV = [&](int st, int tt) {
        const int j0 = tt * 64;
        const uint32_t sb = OKV + st * 36864;
        #pragma unroll
        for (int j = 0; j < 8; j++) {
            const int c = j * 256 + tid;
            const int pl = c >> 9, row = (c >> 3) & 63, ch = c & 7;
            const __nv_bfloat16* src = ((pl & 1) ? g_qkvl : g_qkvh)
                + (rowB + j0 + row) * THREECC + ((pl >> 1) ? 2 * CC : CC) + h64 + ch * 8;
            cp16(sb + pl * 9216 + row * 144 + ch * 16, src);
        }
    };

    issueQ(); CP_COMMIT();
    issueKV(0, 0); CP_COMMIT();
    if (NT > 1) issueKV(1, 1);
    CP_COMMIT();

    const uint32_t koff = (uint32_t)(((((lane >> 4) & 1) * 8 + (lane & 7)) * 144)
                                     + ((lane >> 3) & 1) * 16);
    const uint32_t voff = (uint32_t)(((((lane >> 3) & 1) * 8 + (lane & 7)) * 144)
                                     + ((lane >> 4) & 1) * 16);
    const uint32_t qoff = (uint32_t)(((wm + ((lane >> 3) & 1) * 8 + (lane & 7)) * 144)
                                     + ((lane >> 4) & 1) * 16);

    CP_WAIT(2);
    __syncthreads();
    uint32_t qhf[4][4], qlf[4][4];
    #pragma unroll
    for (int ks = 0; ks < 4; ks++) {
        ldm_x4(qhf[ks], OQ + qoff + ks * 32);
        ldm_x4(qlf[ks], OQ + 18432 + qoff + ks * 32);
    }

    float m0r = -1e30f, m1r = -1e30f, l0r = 0.f, l1r = 0.f;
    float o[8][4] = {};
    const float SC = 0.125f * 1.4426950408889634f;
    const int rq0 = q0 + wm + (lane >> 2);
    const int colb = (lane & 3) * 2;

    for (int t = 0; t < NT; t++) {
        CP_WAIT(1);
        __syncthreads();
        const uint32_t sb  = OKV + (t & 1) * 36864;
        const uint32_t KH = sb, KL = sb + 9216, VH = sb + 18432, VL = sb + 27648;
        const int j0 = t * 64;

        // ---- S = (Q hi/lo).(K hi/lo)^T, 3 terms, term-interleaved
        float s[8][4] = {};
        #pragma unroll
        for (int ks = 0; ks < 4; ks++) {
            uint32_t kh[4][4], kl[4][4];
            #pragma unroll
            for (int g = 0; g < 4; g++) {
                ldm_x4(kh[g], KH + g * 2304 + ks * 32 + koff);
                ldm_x4(kl[g], KL + g * 2304 + ks * 32 + koff);
            }
            #pragma unroll
            for (int g = 0; g < 4; g++) {
                MMA_BF16(s[2*g],   qhf[ks], kh[g][0], kh[g][1]);
                MMA_BF16(s[2*g+1], qhf[ks], kh[g][2], kh[g][3]);
            }
            #pragma unroll
            for (int g = 0; g < 4; g++) {
                MMA_BF16(s[2*g],   qhf[ks], kl[g][0], kl[g][1]);
                MMA_BF16(s[2*g+1], qhf[ks], kl[g][2], kl[g][3]);
            }
            #pragma unroll
            for (int g = 0; g < 4; g++) {
                MMA_BF16(s[2*g],   qlf[ks], kh[g][0], kh[g][1]);
                MMA_BF16(s[2*g+1], qlf[ks], kh[g][2], kh[g][3]);
            }
        }

        // ---- scale (+ causal mask on diagonal tiles)
        if (t >= 2 * qt) {
            #pragma unroll
            for (int nt = 0; nt < 8; nt++) {
                const int c0 = j0 + nt * 8 + colb;
                #pragma unroll
                for (int j = 0; j < 4; j++) {
                    const int cg = c0 + (j & 1);
                    const int rg = rq0 + ((j >> 1) << 3);
                    s[nt][j] = (cg <= rg) ? s[nt][j] * SC : -1e30f;
                }
            }
        } else {
            #pragma unroll
            for (int nt = 0; nt < 8; nt++)
                #pragma unroll
                for (int j = 0; j < 4; j++) s[nt][j] *= SC;
        }

        // ---- online softmax
        float mx0 = -1e30f, mx1 = -1e30f;
        #pragma unroll
        for (int nt = 0; nt < 8; nt++) {
            mx0 = fmaxf(mx0, fmaxf(s[nt][0], s[nt][1]));
            mx1 = fmaxf(mx1, fmaxf(s[nt][2], s[nt][3]));
        }
        mx0 = fmaxf(mx0, __shfl_xor_sync(0xffffffffu, mx0, 1));
        mx0 = fmaxf(mx0, __shfl_xor_sync(0xffffffffu, mx0, 2));
        mx1 = fmaxf(mx1, __shfl_xor_sync(0xffffffffu, mx1, 1));
        mx1 = fmaxf(mx1, __shfl_xor_sync(0xffffffffu, mx1, 2));
        const float mn0 = fmaxf(m0r, mx0), mn1 = fmaxf(m1r, mx1);
        const float a0 = ex2f(m0r - mn0), a1 = ex2f(m1r - mn1);
        m0r = mn0; m1r = mn1;

        float rs0 = 0.f, rs1 = 0.f;
        #pragma unroll
        for (int nt = 0; nt < 8; nt++) {
            s[nt][0] = ex2f(s[nt][0] - mn0);
            s[nt][1] = ex2f(s[nt][1] - mn0);
            s[nt][2] = ex2f(s[nt][2] - mn1);
            s[nt][3] = ex2f(s[nt][3] - mn1);
            rs0 += s[nt][0] + s[nt][1];
            rs1 += s[nt][2] + s[nt][3];
        }
        rs0 += __shfl_xor_sync(0xffffffffu, rs0, 1);
        rs0 += __shfl_xor_sync(0xffffffffu, rs0, 2);
        rs1 += __shfl_xor_sync(0xffffffffu, rs1, 1);
        rs1 += __shfl_xor_sync(0xffffffffu, rs1, 2);
        l0r = l0r * a0 + rs0;
        l1r = l1r * a1 + rs1;

        #pragma unroll
        for (int nt = 0; nt < 8; nt++) {
            o[nt][0] *= a0; o[nt][1] *= a0;
            o[nt][2] *= a1; o[nt][3] *= a1;
        }

        // ---- repack P with hi/lo split
        uint32_t ph[4][4], plo[4][4];
        #pragma unroll
        for (int kt = 0; kt < 4; kt++) {
            pack_split(s[2*kt][0],   s[2*kt][1],   ph[kt][0], plo[kt][0]);
            pack_split(s[2*kt][2],   s[2*kt][3],   ph[kt][1], plo[kt][1]);
            pack_split(s[2*kt+1][0], s[2*kt+1][1], ph[kt][2], plo[kt][2]);
            pack_split(s[2*kt+1][2], s[2*kt+1][3], ph[kt][3], plo[kt][3]);
        }

        // ---- O += P.V, 3 terms, term-interleaved
        #pragma unroll
        for (int kt = 0; kt < 4; kt++) {
            uint32_t vh[4][4], vl[4][4];
            #pragma unroll
            for (int g = 0; g < 4; g++) {
                ldm_x4t(vh[g], VH + kt * 2304 + g * 32 + voff);
                ldm_x4t(vl[g], VL + kt * 2304 + g * 32 + voff);
            }
            #pragma unroll
            for (int g = 0; g < 4; g++) {
                MMA_BF16(o[2*g],   ph[kt],  vh[g][0], vh[g][1]);
                MMA_BF16(o[2*g+1], ph[kt],  vh[g][2], vh[g][3]);
            }
            #pragma unroll
            for (int g = 0; g < 4; g++) {
                MMA_BF16(o[2*g],   ph[kt],  vl[g][0], vl[g][1]);
                MMA_BF16(o[2*g+1], ph[kt],  vl[g][2], vl[g][3]);
            }
            #pragma unroll
            for (int g = 0; g < 4; g++) {
                MMA_BF16(o[2*g],   plo[kt], vh[g][0], vh[g][1]);
                MMA_BF16(o[2*g+1], plo[kt], vh[g][2], vh[g][3]);
            }
        }

        __syncthreads();
        if (t + 2 < NT) issueKV((t + 2) & 1, t + 2);
        CP_COMMIT();
    }

    // ---- epilogue
    const float i0 = 1.0f / l0r, i1 = 1.0f / l1r;
    const size_t r0 = rowB + (size_t)rq0;
    #pragma unroll
    for (int nt = 0; nt < 8; nt++) {
        const int col = h64 + nt * 8 + colb;
        uint32_t hh, ll;
        pack_split(o[nt][0] * i0, o[nt][1] * i0, hh, ll);
        *(uint32_t*)(g_ah + r0 * CC + col) = hh;
        *(uint32_t*)(g_al + r0 * CC + col) = ll;
        pack_split(o[nt][2] * i1, o[nt][3] * i1, hh, ll);
        *(uint32_t*)(g_ah + (r0 + 8) * CC + col) = hh;
        *(uint32_t*)(g_al + (r0 + 8) * CC + col) = ll;
    }
}

// ---------------------------------------------------------------------------
extern "C" void kernel_launch(void* const* d_in, const int* in_sizes, int n_in,
                              void* d_out, int out_size)
{
    const float* x      = (const float*)d_in[0];
    const float* w_attn = (const float*)d_in[1];
    const float* b_attn = (const float*)d_in[2];
    const float* w_proj = (const float*)d_in[3];
    const float* b_proj = (const float*)d_in[4];
    float* out = (float*)d_out;

    __nv_bfloat16 *qkvh, *qkvl, *xh, *xl, *wah, *wal, *wph, *wpl, *ah, *al;
    cudaGetSymbolAddress((void**)&qkvh, g_qkvh);
    cudaGetSymbolAddress((void**)&qkvl, g_qkvl);
    cudaGetSymbolAddress((void**)&xh, g_xh);
    cudaGetSymbolAddress((void**)&xl, g_xl);
    cudaGetSymbolAddress((void**)&wah, g_wah);
    cudaGetSymbolAddress((void**)&wal, g_wal);
    cudaGetSymbolAddress((void**)&wph, g_wph);
    cudaGetSymbolAddress((void**)&wpl, g_wpl);
    cudaGetSymbolAddress((void**)&ah, g_ah);
    cudaGetSymbolAddress((void**)&al, g_al);

    cudaFuncSetAttribute(tc_gemm,
                         cudaFuncAttributeMaxDynamicSharedMemorySize, GEMM_SMEM);
    cudaFuncSetAttribute(flash_tc,
                         cudaFuncAttributeMaxDynamicSharedMemorySize, FLASH_SMEM);

    // 0) input conversions
    {
        const int n4x = MROWS * CC / 4;
        k_split<<<(n4x + 255) / 256, 256>>>((const float4*)x, (uint2*)xh, (uint2*)xl, n4x);
        k_splitT<<<dim3(THREECC / 32, CC / 32), dim3(32, 8)>>>(w_attn, wah, wal, CC, THREECC);
        k_splitT<<<dim3(CC / 32, CC / 32), dim3(32, 8)>>>(w_proj, wph, wpl, CC, CC);
    }

    // 1) qkv planes = split(x @ w_attn + b_attn)
    tc_gemm<<<dim3(THREECC / 128, MROWS / 128), 256, GEMM_SMEM>>>(
        THREECC, xh, xl, wah, wal, b_attn, nullptr, qkvh, qkvl, 1);

    // 2) tensor-core causal flash attention -> planes
    flash_tc<<<dim3(TT / 128, BB * NH), 256, FLASH_SMEM>>>();

    // 3) out = att @ w_proj + b_proj (fp32)
    tc_gemm<<<dim3(CC / 128, MROWS / 128), 256, GEMM_SMEM>>>(
        CC, ah, al, wph, wpl, b_proj, out, nullptr, nullptr, 0);
}

// round 6
// speedup vs baseline: 4.6295x; 1.0226x over previous
#include <cuda_runtime.h>
#include <cuda_bf16.h>
#include <cstdint>
#include <math.h>

// Problem constants
#define BB 4
#define TT 2048
#define CC 1024
#define NH 16
#define HSZ 64
#define MROWS (BB*TT)        // 8192
#define THREECC (3*CC)       // 3072
#define KD 1024

// ---------------------------------------------------------------------------
// Global scratch (device globals: allocation-free)
// ---------------------------------------------------------------------------
__device__ __nv_bfloat16 g_qkvh[(size_t)MROWS * THREECC];  // qkv hi plane
__device__ __nv_bfloat16 g_qkvl[(size_t)MROWS * THREECC];  // qkv lo plane
__device__ __nv_bfloat16 g_xh[(size_t)MROWS * CC];         // x planes [M][K]
__device__ __nv_bfloat16 g_xl[(size_t)MROWS * CC];
__device__ __nv_bfloat16 g_wah[(size_t)THREECC * CC];      // w_attn^T [N][K]
__device__ __nv_bfloat16 g_wal[(size_t)THREECC * CC];
__device__ __nv_bfloat16 g_wph[(size_t)CC * CC];           // w_proj^T [N][K]
__device__ __nv_bfloat16 g_wpl[(size_t)CC * CC];
__device__ __nv_bfloat16 g_ah[(size_t)MROWS * CC];         // attn out planes
__device__ __nv_bfloat16 g_al[(size_t)MROWS * CC];

// ---------------------------------------------------------------------------
// Helpers (compute_103-safe PTX: cp.async / ldmatrix / mma.sync)
// ---------------------------------------------------------------------------
__device__ __forceinline__ uint32_t smem_u32(const void* p) {
    uint32_t a;
    asm("{ .reg .u64 t; cvta.to.shared.u64 t, %1; cvt.u32.u64 %0, t; }"
        : "=r"(a) : "l"(p));
    return a;
}

__device__ __forceinline__ void cp16(uint32_t dst, const void* src) {
    asm volatile("cp.async.cg.shared.global [%0], [%1], 16;"
                 :: "r"(dst), "l"(src));
}
#define CP_COMMIT() asm volatile("cp.async.commit_group;" ::: "memory")
#define CP_WAIT(n)  asm volatile("cp.async.wait_group %0;" :: "n"(n) : "memory")

__device__ __forceinline__ void ldm_x4(uint32_t* r, uint32_t addr) {
    asm volatile("ldmatrix.sync.aligned.m8n8.x4.shared.b16 {%0,%1,%2,%3}, [%4];"
                 : "=r"(r[0]), "=r"(r[1]), "=r"(r[2]), "=r"(r[3]) : "r"(addr));
}
__device__ __forceinline__ void ldm_x4t(uint32_t* r, uint32_t addr) {
    asm volatile("ldmatrix.sync.aligned.m8n8.x4.trans.shared.b16 {%0,%1,%2,%3}, [%4];"
                 : "=r"(r[0]), "=r"(r[1]), "=r"(r[2]), "=r"(r[3]) : "r"(addr));
}

#define MMA_BF16(acc, a, b0, b1)                                              \
    asm volatile(                                                             \
        "mma.sync.aligned.m16n8k16.row.col.f32.bf16.bf16.f32 "                \
        "{%0,%1,%2,%3},{%4,%5,%6,%7},{%8,%9},{%0,%1,%2,%3};"                  \
        : "+f"((acc)[0]), "+f"((acc)[1]), "+f"((acc)[2]), "+f"((acc)[3])      \
        : "r"((a)[0]), "r"((a)[1]), "r"((a)[2]), "r"((a)[3]),                 \
          "r"(b0), "r"(b1))

__device__ __forceinline__ float ex2f(float x) {
    float y;
    asm("ex2.approx.f32 %0, %1;" : "=f"(y) : "f"(x));
    return y;
}

__device__ __forceinline__ void split2(float x, uint16_t& h, uint16_t& l) {
    __nv_bfloat16 hb = __float2bfloat16_rn(x);
    float r = x - __bfloat162float(hb);
    __nv_bfloat16 lb = __float2bfloat16_rn(r);
    h = *(uint16_t*)&hb;
    l = *(uint16_t*)&lb;
}

__device__ __forceinline__ void pack_split(float a, float b, uint32_t& h, uint32_t& l) {
    __nv_bfloat162 hb = __floats2bfloat162_rn(a, b);
    float ra = a - __low2float(hb);
    float rb = b - __high2float(hb);
    __nv_bfloat162 lb = __floats2bfloat162_rn(ra, rb);
    h = *(uint32_t*)&hb;
    l = *(uint32_t*)&lb;
}

// ---------------------------------------------------------------------------
// fp32 -> bf16 hi/lo planes
// ---------------------------------------------------------------------------
__global__ __launch_bounds__(256) void k_split(
    const float4* __restrict__ s, uint2* __restrict__ h, uint2* __restrict__ l, int n4)
{
    const int i = blockIdx.x * 256 + threadIdx.x;
    if (i >= n4) return;
    const float4 v = s[i];
    uint16_t h0, l0, h1, l1, h2, l2, h3, l3;
    split2(v.x, h0, l0); split2(v.y, h1, l1);
    split2(v.z, h2, l2); split2(v.w, h3, l3);
    h[i] = make_uint2((uint32_t)h0 | ((uint32_t)h1 << 16),
                      (uint32_t)h2 | ((uint32_t)h3 << 16));
    l[i] = make_uint2((uint32_t)l0 | ((uint32_t)l1 << 16),
                      (uint32_t)l2 | ((uint32_t)l3 << 16));
}

// fp32 [K][N] -> planes transposed [N][K]
__global__ __launch_bounds__(256) void k_splitT(
    const float* __restrict__ s, __nv_bfloat16* __restrict__ h,
    __nv_bfloat16* __restrict__ l, int K, int N)
{
    __shared__ float t[32][33];
    const int n0 = blockIdx.x * 32, k0 = blockIdx.y * 32;
    const int tx = threadIdx.x, ty = threadIdx.y;
    #pragma unroll
    for (int j = ty; j < 32; j += 8)
        t[j][tx] = s[(size_t)(k0 + j) * N + n0 + tx];
    __syncthreads();
    #pragma unroll
    for (int j = ty; j < 32; j += 8) {
        const float v = t[tx][j];
        uint16_t hh, ll;
        split2(v, hh, ll);
        const size_t o = (size_t)(n0 + j) * K + k0 + tx;
        h[o] = *(__nv_bfloat16*)&hh;
        l[o] = *(__nv_bfloat16*)&ll;
    }
}

// ---------------------------------------------------------------------------
// Tensor-core GEMM (3-term bf16 split): C = A[M][K] @ Bt[N][K]^T + bias
// 128x128 CTA tile, BK=32, 256 thr, warp tile 64x32.
// 2-stage cp.async pipeline, 80KB smem -> 2 CTAs/SM (regs capped to 128).
// ---------------------------------------------------------------------------
#define STAGE_BYTES (4 * 10240)
#define OFF_AH 0
#define OFF_AL 10240
#define OFF_BH 20480
#define OFF_BL 30720
#define GEMM_SMEM (2 * STAGE_BYTES)   // 81920

__global__ __launch_bounds__(256, 2) void tc_gemm(
    int Ndim,
    const __nv_bfloat16* __restrict__ Ah, const __nv_bfloat16* __restrict__ Al,
    const __nv_bfloat16* __restrict__ Bh, const __nv_bfloat16* __restrict__ Bl,
    const float* __restrict__ bias, float* __restrict__ Cf,
    __nv_bfloat16* __restrict__ Ch, __nv_bfloat16* __restrict__ Cl,
    int planes)
{
    extern __shared__ __align__(128) unsigned char smraw[];
    const uint32_t sb0 = smem_u32(smraw);
    const int tid = threadIdx.x, lane = tid & 31, wid = tid >> 5;
    const int m0 = blockIdx.y * 128, n0 = blockIdx.x * 128;
    const int wm = (wid >> 2) * 64, wn = (wid & 3) * 32;

    const int lr = tid >> 2;
    const int lc = tid & 3;
    const __nv_bfloat16* gAh = Ah + (size_t)(m0 + lr) * KD + lc * 8;
    const __nv_bfloat16* gAl = Al + (size_t)(m0 + lr) * KD + lc * 8;
    const __nv_bfloat16* gBh = Bh + (size_t)(n0 + lr) * KD + lc * 8;
    const __nv_bfloat16* gBl = Bl + (size_t)(n0 + lr) * KD + lc * 8;
    const uint32_t dOff  = (uint32_t)(lr * 80 + lc * 16);
    const uint32_t dOff2 = dOff + 64 * 80;
    const size_t   gOff2 = (size_t)64 * KD;

    auto issue = [&](int stage, int kc) {
        const int k0 = kc * 32;
        const uint32_t sb = sb0 + stage * STAGE_BYTES;
        cp16(sb + OFF_AH + dOff,  gAh + k0);
        cp16(sb + OFF_AH + dOff2, gAh + k0 + gOff2);
        cp16(sb + OFF_AL + dOff,  gAl + k0);
        cp16(sb + OFF_AL + dOff2, gAl + k0 + gOff2);
        cp16(sb + OFF_BH + dOff,  gBh + k0);
        cp16(sb + OFF_BH + dOff2, gBh + k0 + gOff2);
        cp16(sb + OFF_BL + dOff,  gBl + k0);
        cp16(sb + OFF_BL + dOff2, gBl + k0 + gOff2);
    };

    issue(0, 0); CP_COMMIT();
    issue(1, 1); CP_COMMIT();

    float acc[4][4][4] = {};

    const uint32_t aRowOff  = (uint32_t)((wm + (lane & 15)) * 80);
    const uint32_t aColHalf = (uint32_t)((lane >> 4) * 16);
    const uint32_t bRowOff  = (uint32_t)((wn + (lane >> 4) * 8 + (lane & 7)) * 80);
    const uint32_t bColHalf = (uint32_t)(((lane >> 3) & 1) * 16);

    for (int c = 0; c < 32; c++) {
        CP_WAIT(1);
        __syncthreads();

        const uint32_t sb = sb0 + (c & 1) * STAGE_BYTES;
        #pragma unroll
        for (int ks = 0; ks < 2; ks++) {
            uint32_t ah[4][4], al[4][4], bh[2][4], bl[2][4];
            const uint32_t acol = (uint32_t)(ks * 32) + aColHalf;
            const uint32_t bcol = (uint32_t)(ks * 32) + bColHalf;
            #pragma unroll
            for (int mt = 0; mt < 4; mt++) {
                ldm_x4(ah[mt], sb + OFF_AH + aRowOff + (uint32_t)(mt * 16 * 80) + acol);
                ldm_x4(al[mt], sb + OFF_AL + aRowOff + (uint32_t)(mt * 16 * 80) + acol);
            }
            #pragma unroll
            for (int p = 0; p < 2; p++) {
                ldm_x4(bh[p], sb + OFF_BH + bRowOff + (uint32_t)(p * 16 * 80) + bcol);
                ldm_x4(bl[p], sb + OFF_BL + bRowOff + (uint32_t)(p * 16 * 80) + bcol);
            }
            #pragma unroll
            for (int mt = 0; mt < 4; mt++)
                #pragma unroll
                for (int nt = 0; nt < 4; nt++) {
                    const uint32_t* bp = &bh[nt >> 1][(nt & 1) * 2];
                    MMA_BF16(acc[mt][nt], ah[mt], bp[0], bp[1]);   // hi*hi
                }
            #pragma unroll
            for (int mt = 0; mt < 4; mt++)
                #pragma unroll
                for (int nt = 0; nt < 4; nt++) {
                    const uint32_t* bp = &bl[nt >> 1][(nt & 1) * 2];
                    MMA_BF16(acc[mt][nt], ah[mt], bp[0], bp[1]);   // hi*lo
                }
            #pragma unroll
            for (int mt = 0; mt < 4; mt++)
                #pragma unroll
                for (int nt = 0; nt < 4; nt++) {
                    const uint32_t* bp = &bh[nt >> 1][(nt & 1) * 2];
                    MMA_BF16(acc[mt][nt], al[mt], bp[0], bp[1]);   // lo*hi
                }
        }
        __syncthreads();
        if (c + 2 < 32) issue(c & 1, c + 2);
        CP_COMMIT();
    }

    const int er = m0 + wm + (lane >> 2);
    const int ec = n0 + wn + (lane & 3) * 2;
    #pragma unroll
    for (int mt = 0; mt < 4; mt++) {
        #pragma unroll
        for (int nt = 0; nt < 4; nt++) {
            const int r = er + mt * 16;
            const int cn = ec + nt * 8;
            const float b0 = bias[cn], b1 = bias[cn + 1];
            const float v0 = acc[mt][nt][0] + b0, v1 = acc[mt][nt][1] + b1;
            const float v2 = acc[mt][nt][2] + b0, v3 = acc[mt][nt][3] + b1;
            if (!planes) {
                *(float2*)(Cf + (size_t)r * Ndim + cn) = make_float2(v0, v1);
                *(float2*)(Cf + (size_t)(r + 8) * Ndim + cn) = make_float2(v2, v3);
            } else {
                uint32_t hh, ll;
                pack_split(v0, v1, hh, ll);
                *(uint32_t*)(Ch + (size_t)r * Ndim + cn) = hh;
                *(uint32_t*)(Cl + (size_t)r * Ndim + cn) = ll;
                pack_split(v2, v3, hh, ll);
                *(uint32_t*)(Ch + (size_t)(r + 8) * Ndim + cn) = hh;
                *(uint32_t*)(Cl + (size_t)(r + 8) * Ndim + cn) = ll;
            }
        }
    }
}

// ---------------------------------------------------------------------------
// Tensor-core causal flash attention, v2: high occupancy.
// CTA = 128 threads (4 warps) x 64 queries; warp owns 16 rows.
// Q staged through KV buffer 0 once -> register fragments; then 2-stage
// KV pipeline in 2 x 36864 B smem => 3 CTAs/SM (12 warps).
// ---------------------------------------------------------------------------
#define FLASH_SMEM (2 * 36864)

__global__ __launch_bounds__(128, 3) void flash_tc()
{
    extern __shared__ __align__(128) unsigned char fsm[];
    const uint32_t OKV = smem_u32(fsm);
    const int tid = threadIdx.x, lane = tid & 31, wid = tid >> 5;
    const int qt = (int)(gridDim.x - 1 - blockIdx.x);   // heavy CTAs first
    const int b = blockIdx.y >> 4, h = blockIdx.y & 15;
    const int q0 = qt * 64, wm = wid * 16;
    const size_t rowB = (size_t)b * TT;
    const int h64 = h * 64;
    const int NT = qt + 1;

    auto issueQ = [&]() {   // 2 planes x 64 rows x 8 chunks -> KV buffer 0
        #pragma unroll
        for (int j = 0; j < 8; j++) {
            const int c = j * 128 + tid;
            const int pl = c >> 9, row = (c >> 3) & 63, ch = c & 7;
            const __nv_bfloat16* src = (pl ? g_qkvl : g_qkvh)
                + (rowB + q0 + row) * THREECC + h64 + ch * 8;
            cp16(OKV + pl * 9216 + row * 144 + ch * 16, src);
        }
    };
    auto issueKV = [&](int st, int tt) {   // 4 planes x 64 rows x 8 chunks
        const int j0 = tt * 64;
        const uint32_t sb = OKV + st * 36864;
        #pragma unroll
        for (int j = 0; j < 16; j++) {
            const int c = j * 128 + tid;
            const int pl = c >> 9, row = (c >> 3) & 63, ch = c & 7;
            const __nv_bfloat16* src = ((pl & 1) ? g_qkvl : g_qkvh)
                + (rowB + j0 + row) * THREECC + ((pl >> 1) ? 2 * CC : CC) + h64 + ch * 8;
            cp16(sb + pl * 9216 + row * 144 + ch * 16, src);
        }
    };

    const uint32_t koff = (uint32_t)(((((lane >> 4) & 1) * 8 + (lane & 7)) * 144)
                                     + ((lane >> 3) & 1) * 16);
    const uint32_t voff = (uint32_t)(((((lane >> 3) & 1) * 8 + (lane & 7)) * 144)
                                     + ((lane >> 4) & 1) * 16);
    const uint32_t qoff = (uint32_t)(((wm + ((lane >> 3) & 1) * 8 + (lane & 7)) * 144)
                                     + ((lane >> 4) & 1) * 16);

    // ---- stage Q through buffer 0, pull to register fragments
    issueQ(); CP_COMMIT();
    CP_WAIT(0);
    __syncthreads();
    uint32_t qhf[4][4], qlf[4][4];
    #pragma unroll
    for (int ks = 0; ks < 4; ks++) {
        ldm_x4(qhf[ks], OKV + qoff + ks * 32);
        ldm_x4(qlf[ks], OKV + 9216 + qoff + ks * 32);
    }
    __syncthreads();   // buffer 0 free again

    // ---- start KV pipeline
    issueKV(0, 0); CP_COMMIT();
    if (NT > 1) issueKV(1, 1);
    CP_COMMIT();

    float m0r = -1e30f, m1r = -1e30f, l0r = 0.f, l1r = 0.f;
    float o[8][4] = {};
    const float SC = 0.125f * 1.4426950408889634f;
    const int rq0 = q0 + wm + (lane >> 2);
    const int colb = (lane & 3) * 2;

    for (int t = 0; t < NT; t++) {
        CP_WAIT(1);
        __syncthreads();
        const uint32_t sb  = OKV + (t & 1) * 36864;
        const uint32_t KH = sb, KL = sb + 9216, VH = sb + 18432, VL = sb + 27648;
        const int j0 = t * 64;

        // ---- S = (Q hi/lo).(K hi/lo)^T, 3 terms, term-interleaved
        float s[8][4] = {};
        #pragma unroll
        for (int ks = 0; ks < 4; ks++) {
            uint32_t kh[4][4], kl[4][4];
            #pragma unroll
            for (int g = 0; g < 4; g++) {
                ldm_x4(kh[g], KH + g * 2304 + ks * 32 + koff);
                ldm_x4(kl[g], KL + g * 2304 + ks * 32 + koff);
            }
            #pragma unroll
            for (int g = 0; g < 4; g++) {
                MMA_BF16(s[2*g],   qhf[ks], kh[g][0], kh[g][1]);
                MMA_BF16(s[2*g+1], qhf[ks], kh[g][2], kh[g][3]);
            }
            #pragma unroll
            for (int g = 0; g < 4; g++) {
                MMA_BF16(s[2*g],   qhf[ks], kl[g][0], kl[g][1]);
                MMA_BF16(s[2*g+1], qhf[ks], kl[g][2], kl[g][3]);
            }
            #pragma unroll
            for (int g = 0; g < 4; g++) {
                MMA_BF16(s[2*g],   qlf[ks], kh[g][0], kh[g][1]);
                MMA_BF16(s[2*g+1], qlf[ks], kh[g][2], kh[g][3]);
            }
        }

        // ---- scale (+ causal mask on diagonal tile)
        if (t == qt) {
            #pragma unroll
            for (int nt = 0; nt < 8; nt++) {
                const int c0 = j0 + nt * 8 + colb;
                #pragma unroll
                for (int j = 0; j < 4; j++) {
                    const int cg = c0 + (j & 1);
                    const int rg = rq0 + ((j >> 1) << 3);
                    s[nt][j] = (cg <= rg) ? s[nt][j] * SC : -1e30f;
                }
            }
        } else {
            #pragma unroll
            for (int nt = 0; nt < 8; nt++)
                #pragma unroll
                for (int j = 0; j < 4; j++) s[nt][j] *= SC;
        }

        // ---- online softmax
        float mx0 = -1e30f, mx1 = -1e30f;
        #pragma unroll
        for (int nt = 0; nt < 8; nt++) {
            mx0 = fmaxf(mx0, fmaxf(s[nt][0], s[nt][1]));
            mx1 = fmaxf(mx1, fmaxf(s[nt][2], s[nt][3]));
        }
        mx0 = fmaxf(mx0, __shfl_xor_sync(0xffffffffu, mx0, 1));
        mx0 = fmaxf(mx0, __shfl_xor_sync(0xffffffffu, mx0, 2));
        mx1 = fmaxf(mx1, __shfl_xor_sync(0xffffffffu, mx1, 1));
        mx1 = fmaxf(mx1, __shfl_xor_sync(0xffffffffu, mx1, 2));
        const float mn0 = fmaxf(m0r, mx0), mn1 = fmaxf(m1r, mx1);
        const float a0 = ex2f(m0r - mn0), a1 = ex2f(m1r - mn1);
        m0r = mn0; m1r = mn1;

        float rs0 = 0.f, rs1 = 0.f;
        #pragma unroll
        for (int nt = 0; nt < 8; nt++) {
            s[nt][0] = ex2f(s[nt][0] - mn0);
            s[nt][1] = ex2f(s[nt][1] - mn0);
            s[nt][2] = ex2f(s[nt][2] - mn1);
            s[nt][3] = ex2f(s[nt][3] - mn1);
            rs0 += s[nt][0] + s[nt][1];
            rs1 += s[nt][2] + s[nt][3];
        }
        rs0 += __shfl_xor_sync(0xffffffffu, rs0, 1);
        rs0 += __shfl_xor_sync(0xffffffffu, rs0, 2);
        rs1 += __shfl_xor_sync(0xffffffffu, rs1, 1);
        rs1 += __shfl_xor_sync(0xffffffffu, rs1, 2);
        l0r = l0r * a0 + rs0;
        l1r = l1r * a1 + rs1;

        #pragma unroll
        for (int nt = 0; nt < 8; nt++) {
            o[nt][0] *= a0; o[nt][1] *= a0;
            o[nt][2] *= a1; o[nt][3] *= a1;
        }

        // ---- repack P with hi/lo split
        uint32_t ph[4][4], plo[4][4];
        #pragma unroll
        for (int kt = 0; kt < 4; kt++) {
            pack_split(s[2*kt][0],   s[2*kt][1],   ph[kt][0], plo[kt][0]);
            pack_split(s[2*kt][2],   s[2*kt][3],   ph[kt][1], plo[kt][1]);
            pack_split(s[2*kt+1][0], s[2*kt+1][1], ph[kt][2], plo[kt][2]);
            pack_split(s[2*kt+1][2], s[2*kt+1][3], ph[kt][3], plo[kt][3]);
        }

        // ---- O += P.V, 3 terms, term-interleaved
        #pragma unroll
        for (int kt = 0; kt < 4; kt++) {
            uint32_t vh[4][4], vl[4][4];
            #pragma unroll
            for (int g = 0; g < 4; g++) {
                ldm_x4t(vh[g], VH + kt * 2304 + g * 32 + voff);
                ldm_x4t(vl[g], VL + kt * 2304 + g * 32 + voff);
            }
            #pragma unroll
            for (int g = 0; g < 4; g++) {
                MMA_BF16(o[2*g],   ph[kt],  vh[g][0], vh[g][1]);
                MMA_BF16(o[2*g+1], ph[kt],  vh[g][2], vh[g][3]);
            }
            #pragma unroll
            for (int g = 0; g < 4; g++) {
                MMA_BF16(o[2*g],   ph[kt],  vl[g][0], vl[g][1]);
                MMA_BF16(o[2*g+1], ph[kt],  vl[g][2], vl[g][3]);
            }
            #pragma unroll
            for (int g = 0; g < 4; g++) {
                MMA_BF16(o[2*g],   plo[kt], vh[g][0], vh[g][1]);
                MMA_BF16(o[2*g+1], plo[kt], vh[g][2], vh[g][3]);
            }
        }

        __syncthreads();
        if (t + 2 < NT) issueKV(t & 1, t + 2);
        CP_COMMIT();
    }

    // ---- epilogue
    const float i0 = 1.0f / l0r, i1 = 1.0f / l1r;
    const size_t r0 = rowB + (size_t)rq0;
    #pragma unroll
    for (int nt = 0; nt < 8; nt++) {
        const int col = h64 + nt * 8 + colb;
        uint32_t hh, ll;
        pack_split(o[nt][0] * i0, o[nt][1] * i0, hh, ll);
        *(uint32_t*)(g_ah + r0 * CC + col) = hh;
        *(uint32_t*)(g_al + r0 * CC + col) = ll;
        pack_split(o[nt][2] * i1, o[nt][3] * i1, hh, ll);
        *(uint32_t*)(g_ah + (r0 + 8) * CC + col) = hh;
        *(uint32_t*)(g_al + (r0 + 8) * CC + col) = ll;
    }
}

// ---------------------------------------------------------------------------
extern "C" void kernel_launch(void* const* d_in, const int* in_sizes, int n_in,
                              void* d_out, int out_size)
{
    const float* x      = (const float*)d_in[0];
    const float* w_attn = (const float*)d_in[1];
    const float* b_attn = (const float*)d_in[2];
    const float* w_proj = (const float*)d_in[3];
    const float* b_proj = (const float*)d_in[4];
    float* out = (float*)d_out;

    __nv_bfloat16 *qkvh, *qkvl, *xh, *xl, *wah, *wal, *wph, *wpl, *ah, *al;
    cudaGetSymbolAddress((void**)&qkvh, g_qkvh);
    cudaGetSymbolAddress((void**)&qkvl, g_qkvl);
    cudaGetSymbolAddress((void**)&xh, g_xh);
    cudaGetSymbolAddress((void**)&xl, g_xl);
    cudaGetSymbolAddress((void**)&wah, g_wah);
    cudaGetSymbolAddress((void**)&wal, g_wal);
    cudaGetSymbolAddress((void**)&wph, g_wph);
    cudaGetSymbolAddress((void**)&wpl, g_wpl);
    cudaGetSymbolAddress((void**)&ah, g_ah);
    cudaGetSymbolAddress((void**)&al, g_al);

    cudaFuncSetAttribute(tc_gemm,
                         cudaFuncAttributeMaxDynamicSharedMemorySize, GEMM_SMEM);
    cudaFuncSetAttribute(flash_tc,
                         cudaFuncAttributeMaxDynamicSharedMemorySize, FLASH_SMEM);

    // 0) input conversions
    {
        const int n4x = MROWS * CC / 4;
        k_split<<<(n4x + 255) / 256, 256>>>((const float4*)x, (uint2*)xh, (uint2*)xl, n4x);
        k_splitT<<<dim3(THREECC / 32, CC / 32), dim3(32, 8)>>>(w_attn, wah, wal, CC, THREECC);
        k_splitT<<<dim3(CC / 32, CC / 32), dim3(32, 8)>>>(w_proj, wph, wpl, CC, CC);
    }

    // 1) qkv planes = split(x @ w_attn + b_attn)
    tc_gemm<<<dim3(THREECC / 128, MROWS / 128), 256, GEMM_SMEM>>>(
        THREECC, xh, xl, wah, wal, b_attn, nullptr, qkvh, qkvl, 1);

    // 2) tensor-core causal flash attention -> planes (3 CTAs/SM)
    flash_tc<<<dim3(TT / 64, BB * NH), 128, FLASH_SMEM>>>();

    // 3) out = att @ w_proj + b_proj (fp32)
    tc_gemm<<<dim3(CC / 128, MROWS / 128), 256, GEMM_SMEM>>>(
        CC, ah, al, wph, wpl, b_proj, out, nullptr, nullptr, 0);
}

// round 7
// speedup vs baseline: 6.4441x; 1.3920x over previous
#include <cuda_runtime.h>
#include <cuda_fp16.h>
#include <cstdint>
#include <math.h>

// Problem constants
#define BB 4
#define TT 2048
#define CC 1024
#define NH 16
#define HSZ 64
#define MROWS (BB*TT)        // 8192
#define THREECC (3*CC)       // 3072
#define KD 1024

// ---------------------------------------------------------------------------
// Global scratch (device globals: allocation-free). fp16 planes.
// ---------------------------------------------------------------------------
__device__ __half g_qkvh[(size_t)MROWS * THREECC];  // qkv hi plane
__device__ __half g_qkvl[(size_t)MROWS * THREECC];  // qkv lo plane (K,V terms)
__device__ __half g_xh[(size_t)MROWS * CC];         // x hi plane [M][K]
__device__ __half g_wah[(size_t)THREECC * CC];      // w_attn^T hi [N][K]
__device__ __half g_wal[(size_t)THREECC * CC];      // w_attn^T lo
__device__ __half g_wph[(size_t)CC * CC];           // w_proj^T hi [N][K]
__device__ __half g_wpl[(size_t)CC * CC];           // w_proj^T lo
__device__ __half g_ah[(size_t)MROWS * CC];         // attn out hi plane

// ---------------------------------------------------------------------------
// Helpers (compute_103-safe PTX: cp.async / ldmatrix / mma.sync)
// ---------------------------------------------------------------------------
__device__ __forceinline__ uint32_t smem_u32(const void* p) {
    uint32_t a;
    asm("{ .reg .u64 t; cvta.to.shared.u64 t, %1; cvt.u32.u64 %0, t; }"
        : "=r"(a) : "l"(p));
    return a;
}

__device__ __forceinline__ void cp16(uint32_t dst, const void* src) {
    asm volatile("cp.async.cg.shared.global [%0], [%1], 16;"
                 :: "r"(dst), "l"(src));
}
#define CP_COMMIT() asm volatile("cp.async.commit_group;" ::: "memory")
#define CP_WAIT(n)  asm volatile("cp.async.wait_group %0;" :: "n"(n) : "memory")

__device__ __forceinline__ void ldm_x4(uint32_t* r, uint32_t addr) {
    asm volatile("ldmatrix.sync.aligned.m8n8.x4.shared.b16 {%0,%1,%2,%3}, [%4];"
                 : "=r"(r[0]), "=r"(r[1]), "=r"(r[2]), "=r"(r[3]) : "r"(addr));
}
__device__ __forceinline__ void ldm_x4t(uint32_t* r, uint32_t addr) {
    asm volatile("ldmatrix.sync.aligned.m8n8.x4.trans.shared.b16 {%0,%1,%2,%3}, [%4];"
                 : "=r"(r[0]), "=r"(r[1]), "=r"(r[2]), "=r"(r[3]) : "r"(addr));
}

#define MMA_F16(acc, a, b0, b1)                                               \
    asm volatile(                                                             \
        "mma.sync.aligned.m16n8k16.row.col.f32.f16.f16.f32 "                  \
        "{%0,%1,%2,%3},{%4,%5,%6,%7},{%8,%9},{%0,%1,%2,%3};"                  \
        : "+f"((acc)[0]), "+f"((acc)[1]), "+f"((acc)[2]), "+f"((acc)[3])      \
        : "r"((a)[0]), "r"((a)[1]), "r"((a)[2]), "r"((a)[3]),                 \
          "r"(b0), "r"(b1))

__device__ __forceinline__ float ex2f(float x) {
    float y;
    asm("ex2.approx.f32 %0, %1;" : "=f"(y) : "f"(x));
    return y;
}

__device__ __forceinline__ void split2h(float x, uint16_t& h, uint16_t& l) {
    __half hb = __float2half_rn(x);
    __half lb = __float2half_rn(x - __half2float(hb));
    h = *(uint16_t*)&hb;
    l = *(uint16_t*)&lb;
}

__device__ __forceinline__ uint32_t pack_h2(float a, float b) {
    __half2 p = __floats2half2_rn(a, b);
    return *(uint32_t*)&p;
}

__device__ __forceinline__ void pack_split_h(float a, float b, uint32_t& h, uint32_t& l) {
    __half2 hb = __floats2half2_rn(a, b);
    float ra = a - __low2float(hb);
    float rb = b - __high2float(hb);
    __half2 lb = __floats2half2_rn(ra, rb);
    h = *(uint32_t*)&hb;
    l = *(uint32_t*)&lb;
}

// ---------------------------------------------------------------------------
// fp32 -> fp16 (hi only) cvt
// ---------------------------------------------------------------------------
__global__ __launch_bounds__(256) void k_cvt(
    const float4* __restrict__ s, uint2* __restrict__ h, int n4)
{
    const int i = blockIdx.x * 256 + threadIdx.x;
    if (i >= n4) return;
    const float4 v = s[i];
    h[i] = make_uint2(pack_h2(v.x, v.y), pack_h2(v.z, v.w));
}

// fp32 [K][N] -> fp16 hi/lo planes transposed [N][K]
__global__ __launch_bounds__(256) void k_splitT(
    const float* __restrict__ s, __half* __restrict__ h,
    __half* __restrict__ l, int K, int N)
{
    __shared__ float t[32][33];
    const int n0 = blockIdx.x * 32, k0 = blockIdx.y * 32;
    const int tx = threadIdx.x, ty = threadIdx.y;
    #pragma unroll
    for (int j = ty; j < 32; j += 8)
        t[j][tx] = s[(size_t)(k0 + j) * N + n0 + tx];
    __syncthreads();
    #pragma unroll
    for (int j = ty; j < 32; j += 8) {
        const float v = t[tx][j];
        uint16_t hh, ll;
        split2h(v, hh, ll);
        const size_t o = (size_t)(n0 + j) * K + k0 + tx;
        h[o] = *(__half*)&hh;
        l[o] = *(__half*)&ll;
    }
}

// ---------------------------------------------------------------------------
// Tensor-core GEMM (2-term fp16 split): C = Ah[M][K] @ (Bh+Bl)[N][K]^T + bias
// 128x128 CTA tile, BK=32, 256 thr, warp tile 64x32.
// 3 planes/stage (Ah,Bh,Bl) x 30720B, 3-stage cp.async, 2 CTAs/SM.
// ---------------------------------------------------------------------------
#define STAGE_BYTES 30720
#define OFF_A  0
#define OFF_BH 10240
#define OFF_BL 20480
#define GEMM_SMEM (3 * STAGE_BYTES)   // 92160

__global__ __launch_bounds__(256, 2) void tc_gemm(
    int Ndim,
    const __half* __restrict__ Ah,
    const __half* __restrict__ Bh, const __half* __restrict__ Bl,
    const float* __restrict__ bias, float* __restrict__ Cf,
    __half* __restrict__ Ch, __half* __restrict__ Cl,
    int planes)
{
    extern __shared__ __align__(128) unsigned char smraw[];
    const uint32_t sb0 = smem_u32(smraw);
    const int tid = threadIdx.x, lane = tid & 31, wid = tid >> 5;
    const int m0 = blockIdx.y * 128, n0 = blockIdx.x * 128;
    const int wm = (wid >> 2) * 64, wn = (wid & 3) * 32;

    const int lr = tid >> 2;
    const int lc = tid & 3;
    const __half* gA  = Ah + (size_t)(m0 + lr) * KD + lc * 8;
    const __half* gBh = Bh + (size_t)(n0 + lr) * KD + lc * 8;
    const __half* gBl = Bl + (size_t)(n0 + lr) * KD + lc * 8;
    const uint32_t dOff  = (uint32_t)(lr * 80 + lc * 16);
    const uint32_t dOff2 = dOff + 64 * 80;
    const size_t   gOff2 = (size_t)64 * KD;

    auto issue = [&](int stage, int kc) {
        const int k0 = kc * 32;
        const uint32_t sb = sb0 + stage * STAGE_BYTES;
        cp16(sb + OFF_A  + dOff,  gA  + k0);
        cp16(sb + OFF_A  + dOff2, gA  + k0 + gOff2);
        cp16(sb + OFF_BH + dOff,  gBh + k0);
        cp16(sb + OFF_BH + dOff2, gBh + k0 + gOff2);
        cp16(sb + OFF_BL + dOff,  gBl + k0);
        cp16(sb + OFF_BL + dOff2, gBl + k0 + gOff2);
    };

    issue(0, 0); CP_COMMIT();
    issue(1, 1); CP_COMMIT();
    issue(2, 2); CP_COMMIT();

    float acc[4][4][4] = {};

    const uint32_t aRowOff  = (uint32_t)((wm + (lane & 15)) * 80);
    const uint32_t aColHalf = (uint32_t)((lane >> 4) * 16);
    const uint32_t bRowOff  = (uint32_t)((wn + (lane >> 4) * 8 + (lane & 7)) * 80);
    const uint32_t bColHalf = (uint32_t)(((lane >> 3) & 1) * 16);

    int stg = 0;
    for (int c = 0; c < 32; c++) {
        CP_WAIT(2);
        __syncthreads();

        const uint32_t sb = sb0 + stg * STAGE_BYTES;
        #pragma unroll
        for (int ks = 0; ks < 2; ks++) {
            uint32_t ah[4][4], bh[2][4], bl[2][4];
            const uint32_t acol = (uint32_t)(ks * 32) + aColHalf;
            const uint32_t bcol = (uint32_t)(ks * 32) + bColHalf;
            #pragma unroll
            for (int mt = 0; mt < 4; mt++)
                ldm_x4(ah[mt], sb + OFF_A + aRowOff + (uint32_t)(mt * 16 * 80) + acol);
            #pragma unroll
            for (int p = 0; p < 2; p++) {
                ldm_x4(bh[p], sb + OFF_BH + bRowOff + (uint32_t)(p * 16 * 80) + bcol);
                ldm_x4(bl[p], sb + OFF_BL + bRowOff + (uint32_t)(p * 16 * 80) + bcol);
            }
            #pragma unroll
            for (int mt = 0; mt < 4; mt++)
                #pragma unroll
                for (int nt = 0; nt < 4; nt++) {
                    const uint32_t* bp = &bh[nt >> 1][(nt & 1) * 2];
                    MMA_F16(acc[mt][nt], ah[mt], bp[0], bp[1]);   // Ah*Bh
                }
            #pragma unroll
            for (int mt = 0; mt < 4; mt++)
                #pragma unroll
                for (int nt = 0; nt < 4; nt++) {
                    const uint32_t* bp = &bl[nt >> 1][(nt & 1) * 2];
                    MMA_F16(acc[mt][nt], ah[mt], bp[0], bp[1]);   // Ah*Bl
                }
        }
        __syncthreads();
        if (c + 3 < 32) issue(stg, c + 3);
        CP_COMMIT();
        stg = (stg == 2) ? 0 : stg + 1;
    }

    const int er = m0 + wm + (lane >> 2);
    const int ec = n0 + wn + (lane & 3) * 2;
    #pragma unroll
    for (int mt = 0; mt < 4; mt++) {
        #pragma unroll
        for (int nt = 0; nt < 4; nt++) {
            const int r = er + mt * 16;
            const int cn = ec + nt * 8;
            const float b0 = bias[cn], b1 = bias[cn + 1];
            const float v0 = acc[mt][nt][0] + b0, v1 = acc[mt][nt][1] + b1;
            const float v2 = acc[mt][nt][2] + b0, v3 = acc[mt][nt][3] + b1;
            if (!planes) {
                *(float2*)(Cf + (size_t)r * Ndim + cn) = make_float2(v0, v1);
                *(float2*)(Cf + (size_t)(r + 8) * Ndim + cn) = make_float2(v2, v3);
            } else {
                uint32_t hh, ll;
                pack_split_h(v0, v1, hh, ll);
                *(uint32_t*)(Ch + (size_t)r * Ndim + cn) = hh;
                *(uint32_t*)(Cl + (size_t)r * Ndim + cn) = ll;
                pack_split_h(v2, v3, hh, ll);
                *(uint32_t*)(Ch + (size_t)(r + 8) * Ndim + cn) = hh;
                *(uint32_t*)(Cl + (size_t)(r + 8) * Ndim + cn) = ll;
            }
        }
    }
}

// ---------------------------------------------------------------------------
// Tensor-core causal flash attention, fp16 2-term.
// CTA = 128 threads (4 warps) x 64 queries; warp owns 16 rows.
// Q hi staged through KV buffer 0 -> register fragments.
// S = Qh.(Kh+Kl)^T ; O += Ph.(Vh+Vl). Output hi plane only.
// Smem: 2 x 36864B (KV: 4 planes x 64 x 144B) => 3 CTAs/SM.
// ---------------------------------------------------------------------------
#define FLASH_SMEM (2 * 36864)

__global__ __launch_bounds__(128, 3) void flash_tc()
{
    extern __shared__ __align__(128) unsigned char fsm[];
    const uint32_t OKV = smem_u32(fsm);
    const int tid = threadIdx.x, lane = tid & 31, wid = tid >> 5;
    const int qt = (int)(gridDim.x - 1 - blockIdx.x);   // heavy CTAs first
    const int b = blockIdx.y >> 4, h = blockIdx.y & 15;
    const int q0 = qt * 64, wm = wid * 16;
    const size_t rowB = (size_t)b * TT;
    const int h64 = h * 64;
    const int NT = qt + 1;

    auto issueQ = [&]() {   // Q hi: 64 rows x 8 chunks -> buffer 0
        #pragma unroll
        for (int j = 0; j < 4; j++) {
            const int c = j * 128 + tid;
            const int row = c >> 3, ch = c & 7;
            const __half* src = g_qkvh + (rowB + q0 + row) * THREECC + h64 + ch * 8;
            cp16(OKV + row * 144 + ch * 16, src);
        }
    };
    auto issueKV = [&](int st, int tt) {   // Kh,Kl,Vh,Vl: 4 planes
        const int j0 = tt * 64;
        const uint32_t sb = OKV + st * 36864;
        #pragma unroll
        for (int j = 0; j < 16; j++) {
            const int c = j * 128 + tid;
            const int pl = c >> 9, row = (c >> 3) & 63, ch = c & 7;
            const __half* src = ((pl & 1) ? g_qkvl : g_qkvh)
                + (rowB + j0 + row) * THREECC + ((pl >> 1) ? 2 * CC : CC) + h64 + ch * 8;
            cp16(sb + pl * 9216 + row * 144 + ch * 16, src);
        }
    };

    const uint32_t koff = (uint32_t)(((((lane >> 4) & 1) * 8 + (lane & 7)) * 144)
                                     + ((lane >> 3) & 1) * 16);
    const uint32_t voff = (uint32_t)(((((lane >> 3) & 1) * 8 + (lane & 7)) * 144)
                                     + ((lane >> 4) & 1) * 16);
    const uint32_t qoff = (uint32_t)(((wm + ((lane >> 3) & 1) * 8 + (lane & 7)) * 144)
                                     + ((lane >> 4) & 1) * 16);

    // ---- stage Q hi through buffer 0, pull to register fragments
    issueQ(); CP_COMMIT();
    CP_WAIT(0);
    __syncthreads();
    uint32_t qhf[4][4];
    #pragma unroll
    for (int ks = 0; ks < 4; ks++)
        ldm_x4(qhf[ks], OKV + qoff + ks * 32);
    __syncthreads();   // buffer 0 free again

    // ---- start KV pipeline
    issueKV(0, 0); CP_COMMIT();
    if (NT > 1) issueKV(1, 1);
    CP_COMMIT();

    float m0r = -1e30f, m1r = -1e30f, l0r = 0.f, l1r = 0.f;
    float o[8][4] = {};
    const float SC = 0.125f * 1.4426950408889634f;
    const int rq0 = q0 + wm + (lane >> 2);
    const int colb = (lane & 3) * 2;

    for (int t = 0; t < NT; t++) {
        CP_WAIT(1);
        __syncthreads();
        const uint32_t sb  = OKV + (t & 1) * 36864;
        const uint32_t KH = sb, KL = sb + 9216, VH = sb + 18432, VL = sb + 27648;
        const int j0 = t * 64;

        // ---- S = Qh.(Kh+Kl)^T, 2 terms
        float s[8][4] = {};
        #pragma unroll
        for (int ks = 0; ks < 4; ks++) {
            uint32_t kh[4][4], kl[4][4];
            #pragma unroll
            for (int g = 0; g < 4; g++) {
                ldm_x4(kh[g], KH + g * 2304 + ks * 32 + koff);
                ldm_x4(kl[g], KL + g * 2304 + ks * 32 + koff);
            }
            #pragma unroll
            for (int g = 0; g < 4; g++) {
                MMA_F16(s[2*g],   qhf[ks], kh[g][0], kh[g][1]);
                MMA_F16(s[2*g+1], qhf[ks], kh[g][2], kh[g][3]);
            }
            #pragma unroll
            for (int g = 0; g < 4; g++) {
                MMA_F16(s[2*g],   qhf[ks], kl[g][0], kl[g][1]);
                MMA_F16(s[2*g+1], qhf[ks], kl[g][2], kl[g][3]);
            }
        }

        // ---- scale (+ causal mask on diagonal tile)
        if (t == qt) {
            #pragma unroll
            for (int nt = 0; nt < 8; nt++) {
                const int c0 = j0 + nt * 8 + colb;
                #pragma unroll
                for (int j = 0; j < 4; j++) {
                    const int cg = c0 + (j & 1);
                    const int rg = rq0 + ((j >> 1) << 3);
                    s[nt][j] = (cg <= rg) ? s[nt][j] * SC : -1e30f;
                }
            }
        } else {
            #pragma unroll
            for (int nt = 0; nt < 8; nt++)
                #pragma unroll
                for (int j = 0; j < 4; j++) s[nt][j] *= SC;
        }

        // ---- online softmax
        float mx0 = -1e30f, mx1 = -1e30f;
        #pragma unroll
        for (int nt = 0; nt < 8; nt++) {
            mx0 = fmaxf(mx0, fmaxf(s[nt][0], s[nt][1]));
            mx1 = fmaxf(mx1, fmaxf(s[nt][2], s[nt][3]));
        }
        mx0 = fmaxf(mx0, __shfl_xor_sync(0xffffffffu, mx0, 1));
        mx0 = fmaxf(mx0, __shfl_xor_sync(0xffffffffu, mx0, 2));
        mx1 = fmaxf(mx1, __shfl_xor_sync(0xffffffffu, mx1, 1));
        mx1 = fmaxf(mx1, __shfl_xor_sync(0xffffffffu, mx1, 2));
        const float mn0 = fmaxf(m0r, mx0), mn1 = fmaxf(m1r, mx1);
        const float a0 = ex2f(m0r - mn0), a1 = ex2f(m1r - mn1);
        m0r = mn0; m1r = mn1;

        float rs0 = 0.f, rs1 = 0.f;
        #pragma unroll
        for (int nt = 0; nt < 8; nt++) {
            s[nt][0] = ex2f(s[nt][0] - mn0);
            s[nt][1] = ex2f(s[nt][1] - mn0);
            s[nt][2] = ex2f(s[nt][2] - mn1);
            s[nt][3] = ex2f(s[nt][3] - mn1);
            rs0 += s[nt][0] + s[nt][1];
            rs1 += s[nt][2] + s[nt][3];
        }
        rs0 += __shfl_xor_sync(0xffffffffu, rs0, 1);
        rs0 += __shfl_xor_sync(0xffffffffu, rs0, 2);
        rs1 += __shfl_xor_sync(0xffffffffu, rs1, 1);
        rs1 += __shfl_xor_sync(0xffffffffu, rs1, 2);
        l0r = l0r * a0 + rs0;
        l1r = l1r * a1 + rs1;

        #pragma unroll
        for (int nt = 0; nt < 8; nt++) {
            o[nt][0] *= a0; o[nt][1] *= a0;
            o[nt][2] *= a1; o[nt][3] *= a1;
        }

        // ---- P -> fp16 (hi only, plain cvt)
        uint32_t ph[4][4];
        #pragma unroll
        for (int kt = 0; kt < 4; kt++) {
            ph[kt][0] = pack_h2(s[2*kt][0],   s[2*kt][1]);
            ph[kt][1] = pack_h2(s[2*kt][2],   s[2*kt][3]);
            ph[kt][2] = pack_h2(s[2*kt+1][0], s[2*kt+1][1]);
            ph[kt][3] = pack_h2(s[2*kt+1][2], s[2*kt+1][3]);
        }

        // ---- O += Ph.(Vh+Vl), 2 terms
        #pragma unroll
        for (int kt = 0; kt < 4; kt++) {
            uint32_t vh[4][4], vl[4][4];
            #pragma unroll
            for (int g = 0; g < 4; g++) {
                ldm_x4t(vh[g], VH + kt * 2304 + g * 32 + voff);
                ldm_x4t(vl[g], VL + kt * 2304 + g * 32 + voff);
            }
            #pragma unroll
            for (int g = 0; g < 4; g++) {
                MMA_F16(o[2*g],   ph[kt], vh[g][0], vh[g][1]);
                MMA_F16(o[2*g+1], ph[kt], vh[g][2], vh[g][3]);
            }
            #pragma unroll
            for (int g = 0; g < 4; g++) {
                MMA_F16(o[2*g],   ph[kt], vl[g][0], vl[g][1]);
                MMA_F16(o[2*g+1], ph[kt], vl[g][2], vl[g][3]);
            }
        }

        __syncthreads();
        if (t + 2 < NT) issueKV(t & 1, t + 2);
        CP_COMMIT();
    }

    // ---- epilogue: normalize, cvt, store hi plane
    const float i0 = 1.0f / l0r, i1 = 1.0f / l1r;
    const size_t r0 = rowB + (size_t)rq0;
    #pragma unroll
    for (int nt = 0; nt < 8; nt++) {
        const int col = h64 + nt * 8 + colb;
        *(uint32_t*)(g_ah + r0 * CC + col)       = pack_h2(o[nt][0] * i0, o[nt][1] * i0);
        *(uint32_t*)(g_ah + (r0 + 8) * CC + col) = pack_h2(o[nt][2] * i1, o[nt][3] * i1);
    }
}

// ---------------------------------------------------------------------------
extern "C" void kernel_launch(void* const* d_in, const int* in_sizes, int n_in,
                              void* d_out, int out_size)
{
    const float* x      = (const float*)d_in[0];
    const float* w_attn = (const float*)d_in[1];
    const float* b_attn = (const float*)d_in[2];
    const float* w_proj = (const float*)d_in[3];
    const float* b_proj = (const float*)d_in[4];
    float* out = (float*)d_out;

    __half *qkvh, *qkvl, *xh, *wah, *wal, *wph, *wpl, *ah;
    cudaGetSymbolAddress((void**)&qkvh, g_qkvh);
    cudaGetSymbolAddress((void**)&qkvl, g_qkvl);
    cudaGetSymbolAddress((void**)&xh, g_xh);
    cudaGetSymbolAddress((void**)&wah, g_wah);
    cudaGetSymbolAddress((void**)&wal, g_wal);
    cudaGetSymbolAddress((void**)&wph, g_wph);
    cudaGetSymbolAddress((void**)&wpl, g_wpl);
    cudaGetSymbolAddress((void**)&ah, g_ah);

    cudaFuncSetAttribute(tc_gemm,
                         cudaFuncAttributeMaxDynamicSharedMemorySize, GEMM_SMEM);
    cudaFuncSetAttribute(flash_tc,
                         cudaFuncAttributeMaxDynamicSharedMemorySize, FLASH_SMEM);

    // 0) input conversions
    {
        const int n4x = MROWS * CC / 4;
        k_cvt<<<(n4x + 255) / 256, 256>>>((const float4*)x, (uint2*)xh, n4x);
        k_splitT<<<dim3(THREECC / 32, CC / 32), dim3(32, 8)>>>(w_attn, wah, wal, CC, THREECC);
        k_splitT<<<dim3(CC / 32, CC / 32), dim3(32, 8)>>>(w_proj, wph, wpl, CC, CC);
    }

    // 1) qkv planes = split(xh @ (w_attn hi+lo) + b_attn)
    tc_gemm<<<dim3(THREECC / 128, MROWS / 128), 256, GEMM_SMEM>>>(
        THREECC, xh, wah, wal, b_attn, nullptr, qkvh, qkvl, 1);

    // 2) fp16 tensor-core causal flash attention -> hi plane
    flash_tc<<<dim3(TT / 64, BB * NH), 128, FLASH_SMEM>>>();

    // 3) out = ah @ (w_proj hi+lo) + b_proj (fp32)
    tc_gemm<<<dim3(CC / 128, MROWS / 128), 256, GEMM_SMEM>>>(
        CC, ah, wph, wpl, b_proj, out, nullptr, nullptr, 0);
}

// round 8
// speedup vs baseline: 6.7190x; 1.0426x over previous
#include <cuda_runtime.h>
#include <cuda_fp16.h>
#include <cstdint>
#include <math.h>

// Problem constants
#define BB 4
#define TT 2048
#define CC 1024
#define NH 16
#define HSZ 64
#define MROWS (BB*TT)        // 8192
#define THREECC (3*CC)       // 3072
#define KD 1024

// ---------------------------------------------------------------------------
// Global scratch (device globals: allocation-free). fp16 planes.
// ---------------------------------------------------------------------------
__device__ __half g_qkvh[(size_t)MROWS * THREECC];  // qkv hi plane
__device__ __half g_qkvl[(size_t)MROWS * THREECC];  // qkv lo plane (K,V terms)
__device__ __half g_xh[(size_t)MROWS * CC];         // x hi plane [M][K]
__device__ __half g_wah[(size_t)THREECC * CC];      // w_attn^T hi [N][K]
__device__ __half g_wal[(size_t)THREECC * CC];      // w_attn^T lo
__device__ __half g_wph[(size_t)CC * CC];           // w_proj^T hi [N][K]
__device__ __half g_wpl[(size_t)CC * CC];           // w_proj^T lo
__device__ __half g_ah[(size_t)MROWS * CC];         // attn out hi plane

// ---------------------------------------------------------------------------
// Helpers (compute_103-safe PTX: cp.async / ldmatrix / mma.sync)
// ---------------------------------------------------------------------------
__device__ __forceinline__ uint32_t smem_u32(const void* p) {
    uint32_t a;
    asm("{ .reg .u64 t; cvta.to.shared.u64 t, %1; cvt.u32.u64 %0, t; }"
        : "=r"(a) : "l"(p));
    return a;
}

__device__ __forceinline__ void cp16(uint32_t dst, const void* src) {
    asm volatile("cp.async.cg.shared.global [%0], [%1], 16;"
                 :: "r"(dst), "l"(src));
}
#define CP_COMMIT() asm volatile("cp.async.commit_group;" ::: "memory")
#define CP_WAIT(n)  asm volatile("cp.async.wait_group %0;" :: "n"(n) : "memory")

__device__ __forceinline__ void ldm_x4(uint32_t* r, uint32_t addr) {
    asm volatile("ldmatrix.sync.aligned.m8n8.x4.shared.b16 {%0,%1,%2,%3}, [%4];"
                 : "=r"(r[0]), "=r"(r[1]), "=r"(r[2]), "=r"(r[3]) : "r"(addr));
}
__device__ __forceinline__ void ldm_x4t(uint32_t* r, uint32_t addr) {
    asm volatile("ldmatrix.sync.aligned.m8n8.x4.trans.shared.b16 {%0,%1,%2,%3}, [%4];"
                 : "=r"(r[0]), "=r"(r[1]), "=r"(r[2]), "=r"(r[3]) : "r"(addr));
}

#define MMA_F16(acc, a, b0, b1)                                               \
    asm volatile(                                                             \
        "mma.sync.aligned.m16n8k16.row.col.f32.f16.f16.f32 "                  \
        "{%0,%1,%2,%3},{%4,%5,%6,%7},{%8,%9},{%0,%1,%2,%3};"                  \
        : "+f"((acc)[0]), "+f"((acc)[1]), "+f"((acc)[2]), "+f"((acc)[3])      \
        : "r"((a)[0]), "r"((a)[1]), "r"((a)[2]), "r"((a)[3]),                 \
          "r"(b0), "r"(b1))

__device__ __forceinline__ float ex2f(float x) {
    float y;
    asm("ex2.approx.f32 %0, %1;" : "=f"(y) : "f"(x));
    return y;
}

__device__ __forceinline__ uint32_t ex2_h2(uint32_t x) {
    uint32_t y;
    asm("ex2.approx.f16x2 %0, %1;" : "=r"(y) : "r"(x));
    return y;
}

__device__ __forceinline__ void split2h(float x, uint16_t& h, uint16_t& l) {
    __half hb = __float2half_rn(x);
    __half lb = __float2half_rn(x - __half2float(hb));
    h = *(uint16_t*)&hb;
    l = *(uint16_t*)&lb;
}

__device__ __forceinline__ uint32_t pack_h2(float a, float b) {
    __half2 p = __floats2half2_rn(a, b);
    return *(uint32_t*)&p;
}

__device__ __forceinline__ void pack_split_h(float a, float b, uint32_t& h, uint32_t& l) {
    __half2 hb = __floats2half2_rn(a, b);
    float ra = a - __low2float(hb);
    float rb = b - __high2float(hb);
    __half2 lb = __floats2half2_rn(ra, rb);
    h = *(uint32_t*)&hb;
    l = *(uint32_t*)&lb;
}

// ---------------------------------------------------------------------------
// fp32 -> fp16 (hi only) cvt
// ---------------------------------------------------------------------------
__global__ __launch_bounds__(256) void k_cvt(
    const float4* __restrict__ s, uint2* __restrict__ h, int n4)
{
    const int i = blockIdx.x * 256 + threadIdx.x;
    if (i >= n4) return;
    const float4 v = s[i];
    h[i] = make_uint2(pack_h2(v.x, v.y), pack_h2(v.z, v.w));
}

// fp32 [K][N] -> fp16 hi/lo planes transposed [N][K]
__global__ __launch_bounds__(256) void k_splitT(
    const float* __restrict__ s, __half* __restrict__ h,
    __half* __restrict__ l, int K, int N)
{
    __shared__ float t[32][33];
    const int n0 = blockIdx.x * 32, k0 = blockIdx.y * 32;
    const int tx = threadIdx.x, ty = threadIdx.y;
    #pragma unroll
    for (int j = ty; j < 32; j += 8)
        t[j][tx] = s[(size_t)(k0 + j) * N + n0 + tx];
    __syncthreads();
    #pragma unroll
    for (int j = ty; j < 32; j += 8) {
        const float v = t[tx][j];
        uint16_t hh, ll;
        split2h(v, hh, ll);
        const size_t o = (size_t)(n0 + j) * K + k0 + tx;
        h[o] = *(__half*)&hh;
        l[o] = *(__half*)&ll;
    }
}

// ---------------------------------------------------------------------------
// Tensor-core GEMM (2-term fp16 split): C = Ah[M][K] @ (Bh+Bl)[N][K]^T + bias
// 128x128 CTA tile, BK=64, 256 thr, warp tile 64x32.
// 3 planes/stage (Ah,Bh,Bl) x 128x144B = 55296B, 2-stage, 2 CTAs/SM.
// 128 MMAs between sync pairs (2x the BK=32 ratio).
// ---------------------------------------------------------------------------
#define STAGE_BYTES (3 * 18432)   // 55296
#define OFF_A  0
#define OFF_BH 18432
#define OFF_BL 36864
#define GEMM_SMEM (2 * STAGE_BYTES)   // 110592

__global__ __launch_bounds__(256, 2) void tc_gemm(
    int Ndim,
    const __half* __restrict__ Ah,
    const __half* __restrict__ Bh, const __half* __restrict__ Bl,
    const float* __restrict__ bias, float* __restrict__ Cf,
    __half* __restrict__ Ch, __half* __restrict__ Cl,
    int planes)
{
    extern __shared__ __align__(128) unsigned char smraw[];
    const uint32_t sb0 = smem_u32(smraw);
    const int tid = threadIdx.x, lane = tid & 31, wid = tid >> 5;
    const int m0 = blockIdx.y * 128, n0 = blockIdx.x * 128;
    const int wm = (wid >> 2) * 64, wn = (wid & 3) * 32;

    const __half* gA  = Ah + (size_t)m0 * KD;
    const __half* gBh = Bh + (size_t)n0 * KD;
    const __half* gBl = Bl + (size_t)n0 * KD;

    auto issue = [&](int stage, int kc) {
        const int k0 = kc * 64;
        const uint32_t sb = sb0 + stage * STAGE_BYTES;
        #pragma unroll
        for (int j = 0; j < 4; j++) {
            const int c = j * 256 + tid;
            const int row = c >> 3, ch = c & 7;
            const uint32_t d = (uint32_t)(row * 144 + ch * 16);
            const size_t g = (size_t)row * KD + k0 + ch * 8;
            cp16(sb + OFF_A  + d, gA  + g);
            cp16(sb + OFF_BH + d, gBh + g);
            cp16(sb + OFF_BL + d, gBl + g);
        }
    };

    issue(0, 0); CP_COMMIT();
    issue(1, 1); CP_COMMIT();

    float acc[4][4][4] = {};

    const uint32_t aRowOff  = (uint32_t)((wm + (lane & 15)) * 144);
    const uint32_t aColHalf = (uint32_t)((lane >> 4) * 16);
    const uint32_t bRowOff  = (uint32_t)((wn + (lane >> 4) * 8 + (lane & 7)) * 144);
    const uint32_t bColHalf = (uint32_t)(((lane >> 3) & 1) * 16);

    for (int c = 0; c < 16; c++) {
        CP_WAIT(1);
        __syncthreads();

        const uint32_t sb = sb0 + (c & 1) * STAGE_BYTES;
        #pragma unroll
        for (int ks = 0; ks < 4; ks++) {
            uint32_t ah[4][4], bh[2][4], bl[2][4];
            const uint32_t acol = (uint32_t)(ks * 32) + aColHalf;
            const uint32_t bcol = (uint32_t)(ks * 32) + bColHalf;
            #pragma unroll
            for (int mt = 0; mt < 4; mt++)
                ldm_x4(ah[mt], sb + OFF_A + aRowOff + (uint32_t)(mt * 16 * 144) + acol);
            #pragma unroll
            for (int p = 0; p < 2; p++) {
                ldm_x4(bh[p], sb + OFF_BH + bRowOff + (uint32_t)(p * 16 * 144) + bcol);
                ldm_x4(bl[p], sb + OFF_BL + bRowOff + (uint32_t)(p * 16 * 144) + bcol);
            }
            #pragma unroll
            for (int mt = 0; mt < 4; mt++)
                #pragma unroll
                for (int nt = 0; nt < 4; nt++) {
                    const uint32_t* bp = &bh[nt >> 1][(nt & 1) * 2];
                    MMA_F16(acc[mt][nt], ah[mt], bp[0], bp[1]);   // Ah*Bh
                }
            #pragma unroll
            for (int mt = 0; mt < 4; mt++)
                #pragma unroll
                for (int nt = 0; nt < 4; nt++) {
                    const uint32_t* bp = &bl[nt >> 1][(nt & 1) * 2];
                    MMA_F16(acc[mt][nt], ah[mt], bp[0], bp[1]);   // Ah*Bl
                }
        }
        __syncthreads();
        if (c + 2 < 16) issue(c & 1, c + 2);
        CP_COMMIT();
    }

    const int er = m0 + wm + (lane >> 2);
    const int ec = n0 + wn + (lane & 3) * 2;
    #pragma unroll
    for (int mt = 0; mt < 4; mt++) {
        #pragma unroll
        for (int nt = 0; nt < 4; nt++) {
            const int r = er + mt * 16;
            const int cn = ec + nt * 8;
            const float b0 = bias[cn], b1 = bias[cn + 1];
            const float v0 = acc[mt][nt][0] + b0, v1 = acc[mt][nt][1] + b1;
            const float v2 = acc[mt][nt][2] + b0, v3 = acc[mt][nt][3] + b1;
            if (!planes) {
                *(float2*)(Cf + (size_t)r * Ndim + cn) = make_float2(v0, v1);
                *(float2*)(Cf + (size_t)(r + 8) * Ndim + cn) = make_float2(v2, v3);
            } else {
                uint32_t hh, ll;
                pack_split_h(v0, v1, hh, ll);
                *(uint32_t*)(Ch + (size_t)r * Ndim + cn) = hh;
                *(uint32_t*)(Cl + (size_t)r * Ndim + cn) = ll;
                pack_split_h(v2, v3, hh, ll);
                *(uint32_t*)(Ch + (size_t)(r + 8) * Ndim + cn) = hh;
                *(uint32_t*)(Cl + (size_t)(r + 8) * Ndim + cn) = ll;
            }
        }
    }
}

// ---------------------------------------------------------------------------
// Tensor-core causal flash attention, fp16 2-term, vectorized softmax:
// exp via ex2.f16x2 (result IS the fp16 P fragment), row-sum via ones-MMA.
// CTA = 128 threads (4 warps) x 64 queries; 3 CTAs/SM.
// ---------------------------------------------------------------------------
#define FLASH_SMEM (2 * 36864)

__global__ __launch_bounds__(128, 3) void flash_tc()
{
    extern __shared__ __align__(128) unsigned char fsm[];
    const uint32_t OKV = smem_u32(fsm);
    const int tid = threadIdx.x, lane = tid & 31, wid = tid >> 5;
    const int qt = (int)(gridDim.x - 1 - blockIdx.x);   // heavy CTAs first
    const int b = blockIdx.y >> 4, h = blockIdx.y & 15;
    const int q0 = qt * 64, wm = wid * 16;
    const size_t rowB = (size_t)b * TT;
    const int h64 = h * 64;
    const int NT = qt + 1;

    auto issueQ = [&]() {
        #pragma unroll
        for (int j = 0; j < 4; j++) {
            const int c = j * 128 + tid;
            const int row = c >> 3, ch = c & 7;
            const __half* src = g_qkvh + (rowB + q0 + row) * THREECC + h64 + ch * 8;
            cp16(OKV + row * 144 + ch * 16, src);
        }
    };
    auto issueKV = [&](int st, int tt) {
        const int j0 = tt * 64;
        const uint32_t sb = OKV + st * 36864;
        #pragma unroll
        for (int j = 0; j < 16; j++) {
            const int c = j * 128 + tid;
            const int pl = c >> 9, row = (c >> 3) & 63, ch = c & 7;
            const __half* src = ((pl & 1) ? g_qkvl : g_qkvh)
                + (rowB + j0 + row) * THREECC + ((pl >> 1) ? 2 * CC : CC) + h64 + ch * 8;
            cp16(sb + pl * 9216 + row * 144 + ch * 16, src);
        }
    };

    const uint32_t koff = (uint32_t)(((((lane >> 4) & 1) * 8 + (lane & 7)) * 144)
                                     + ((lane >> 3) & 1) * 16);
    const uint32_t voff = (uint32_t)(((((lane >> 3) & 1) * 8 + (lane & 7)) * 144)
                                     + ((lane >> 4) & 1) * 16);
    const uint32_t qoff = (uint32_t)(((wm + ((lane >> 3) & 1) * 8 + (lane & 7)) * 144)
                                     + ((lane >> 4) & 1) * 16);

    issueQ(); CP_COMMIT();
    CP_WAIT(0);
    __syncthreads();
    uint32_t qhf[4][4];
    #pragma unroll
    for (int ks = 0; ks < 4; ks++)
        ldm_x4(qhf[ks], OKV + qoff + ks * 32);
    __syncthreads();

    issueKV(0, 0); CP_COMMIT();
    if (NT > 1) issueKV(1, 1);
    CP_COMMIT();

    float m0r = -1e30f, m1r = -1e30f, l0r = 0.f, l1r = 0.f;
    float o[8][4] = {};
    const float SC = 0.125f * 1.4426950408889634f;
    const int rq0 = q0 + wm + (lane >> 2);
    const int colb = (lane & 3) * 2;
    const uint32_t ONE2 = 0x3C003C00u;   // half2(1,1)

    for (int t = 0; t < NT; t++) {
        CP_WAIT(1);
        __syncthreads();
        const uint32_t sb  = OKV + (t & 1) * 36864;
        const uint32_t KH = sb, KL = sb + 9216, VH = sb + 18432, VL = sb + 27648;
        const int j0 = t * 64;

        // ---- S = Qh.(Kh+Kl)^T, 2 terms
        float s[8][4] = {};
        #pragma unroll
        for (int ks = 0; ks < 4; ks++) {
            uint32_t kh[4][4], kl[4][4];
            #pragma unroll
            for (int g = 0; g < 4; g++) {
                ldm_x4(kh[g], KH + g * 2304 + ks * 32 + koff);
                ldm_x4(kl[g], KL + g * 2304 + ks * 32 + koff);
            }
            #pragma unroll
            for (int g = 0; g < 4; g++) {
                MMA_F16(s[2*g],   qhf[ks], kh[g][0], kh[g][1]);
                MMA_F16(s[2*g+1], qhf[ks], kh[g][2], kh[g][3]);
            }
            #pragma unroll
            for (int g = 0; g < 4; g++) {
                MMA_F16(s[2*g],   qhf[ks], kl[g][0], kl[g][1]);
                MMA_F16(s[2*g+1], qhf[ks], kl[g][2], kl[g][3]);
            }
        }

        // ---- scale (+ causal mask on diagonal tile)
        if (t == qt) {
            #pragma unroll
            for (int nt = 0; nt < 8; nt++) {
                const int c0 = j0 + nt * 8 + colb;
                #pragma unroll
                for (int j = 0; j < 4; j++) {
                    const int cg = c0 + (j & 1);
                    const int rg = rq0 + ((j >> 1) << 3);
                    s[nt][j] = (cg <= rg) ? s[nt][j] * SC : -1e30f;
                }
            }
        } else {
            #pragma unroll
            for (int nt = 0; nt < 8; nt++)
                #pragma unroll
                for (int j = 0; j < 4; j++) s[nt][j] *= SC;
        }

        // ---- row max (fp32) + running-max update
        float mx0 = -1e30f, mx1 = -1e30f;
        #pragma unroll
        for (int nt = 0; nt < 8; nt++) {
            mx0 = fmaxf(mx0, fmaxf(s[nt][0], s[nt][1]));
            mx1 = fmaxf(mx1, fmaxf(s[nt][2], s[nt][3]));
        }
        mx0 = fmaxf(mx0, __shfl_xor_sync(0xffffffffu, mx0, 1));
        mx0 = fmaxf(mx0, __shfl_xor_sync(0xffffffffu, mx0, 2));
        mx1 = fmaxf(mx1, __shfl_xor_sync(0xffffffffu, mx1, 1));
        mx1 = fmaxf(mx1, __shfl_xor_sync(0xffffffffu, mx1, 2));
        const float mn0 = fmaxf(m0r, mx0), mn1 = fmaxf(m1r, mx1);
        const float a0 = ex2f(m0r - mn0), a1 = ex2f(m1r - mn1);
        m0r = mn0; m1r = mn1;

        // ---- P = exp2(s - mn) directly in fp16 (ex2.f16x2); masked -> -inf -> 0
        uint32_t ph[4][4];
        #pragma unroll
        for (int kt = 0; kt < 4; kt++) {
            ph[kt][0] = ex2_h2(pack_h2(s[2*kt][0]   - mn0, s[2*kt][1]   - mn0));
            ph[kt][1] = ex2_h2(pack_h2(s[2*kt][2]   - mn1, s[2*kt][3]   - mn1));
            ph[kt][2] = ex2_h2(pack_h2(s[2*kt+1][0] - mn0, s[2*kt+1][1] - mn0));
            ph[kt][3] = ex2_h2(pack_h2(s[2*kt+1][2] - mn1, s[2*kt+1][3] - mn1));
        }

        // ---- row sums via ones-MMA (k-reduction crosses lanes: no shuffles)
        float racc[4] = {0.f, 0.f, 0.f, 0.f};
        #pragma unroll
        for (int kt = 0; kt < 4; kt++)
            MMA_F16(racc, ph[kt], ONE2, ONE2);
        l0r = l0r * a0 + racc[0];
        l1r = l1r * a1 + racc[2];

        // ---- rescale O
        #pragma unroll
        for (int nt = 0; nt < 8; nt++) {
            o[nt][0] *= a0; o[nt][1] *= a0;
            o[nt][2] *= a1; o[nt][3] *= a1;
        }

        // ---- O += Ph.(Vh+Vl), 2 terms
        #pragma unroll
        for (int kt = 0; kt < 4; kt++) {
            uint32_t vh[4][4], vl[4][4];
            #pragma unroll
            for (int g = 0; g < 4; g++) {
                ldm_x4t(vh[g], VH + kt * 2304 + g * 32 + voff);
                ldm_x4t(vl[g], VL + kt * 2304 + g * 32 + voff);
            }
            #pragma unroll
            for (int g = 0; g < 4; g++) {
                MMA_F16(o[2*g],   ph[kt], vh[g][0], vh[g][1]);
                MMA_F16(o[2*g+1], ph[kt], vh[g][2], vh[g][3]);
            }
            #pragma unroll
            for (int g = 0; g < 4; g++) {
                MMA_F16(o[2*g],   ph[kt], vl[g][0], vl[g][1]);
                MMA_F16(o[2*g+1], ph[kt], vl[g][2], vl[g][3]);
            }
        }

        __syncthreads();
        if (t + 2 < NT) issueKV(t & 1, t + 2);
        CP_COMMIT();
    }

    // ---- epilogue: normalize, cvt, store hi plane
    const float i0 = 1.0f / l0r, i1 = 1.0f / l1r;
    const size_t r0 = rowB + (size_t)rq0;
    #pragma unroll
    for (int nt = 0; nt < 8; nt++) {
        const int col = h64 + nt * 8 + colb;
        *(uint32_t*)(g_ah + r0 * CC + col)       = pack_h2(o[nt][0] * i0, o[nt][1] * i0);
        *(uint32_t*)(g_ah + (r0 + 8) * CC + col) = pack_h2(o[nt][2] * i1, o[nt][3] * i1);
    }
}

// ---------------------------------------------------------------------------
extern "C" void kernel_launch(void* const* d_in, const int* in_sizes, int n_in,
                              void* d_out, int out_size)
{
    const float* x      = (const float*)d_in[0];
    const float* w_attn = (const float*)d_in[1];
    const float* b_attn = (const float*)d_in[2];
    const float* w_proj = (const float*)d_in[3];
    const float* b_proj = (const float*)d_in[4];
    float* out = (float*)d_out;

    __half *qkvh, *qkvl, *xh, *wah, *wal, *wph, *wpl, *ah;
    cudaGetSymbolAddress((void**)&qkvh, g_qkvh);
    cudaGetSymbolAddress((void**)&qkvl, g_qkvl);
    cudaGetSymbolAddress((void**)&xh, g_xh);
    cudaGetSymbolAddress((void**)&wah, g_wah);
    cudaGetSymbolAddress((void**)&wal, g_wal);
    cudaGetSymbolAddress((void**)&wph, g_wph);
    cudaGetSymbolAddress((void**)&wpl, g_wpl);
    cudaGetSymbolAddress((void**)&ah, g_ah);

    cudaFuncSetAttribute(tc_gemm,
                         cudaFuncAttributeMaxDynamicSharedMemorySize, GEMM_SMEM);
    cudaFuncSetAttribute(flash_tc,
                         cudaFuncAttributeMaxDynamicSharedMemorySize, FLASH_SMEM);

    // 0) input conversions
    {
        const int n4x = MROWS * CC / 4;
        k_cvt<<<(n4x + 255) / 256, 256>>>((const float4*)x, (uint2*)xh, n4x);
        k_splitT<<<dim3(THREECC / 32, CC / 32), dim3(32, 8)>>>(w_attn, wah, wal, CC, THREECC);
        k_splitT<<<dim3(CC / 32, CC / 32), dim3(32, 8)>>>(w_proj, wph, wpl, CC, CC);
    }

    // 1) qkv planes = split(xh @ (w_attn hi+lo) + b_attn)
    tc_gemm<<<dim3(THREECC / 128, MROWS / 128), 256, GEMM_SMEM>>>(
        THREECC, xh, wah, wal, b_attn, nullptr, qkvh, qkvl, 1);

    // 2) fp16 tensor-core causal flash attention -> hi plane
    flash_tc<<<dim3(TT / 64, BB * NH), 128, FLASH_SMEM>>>();

    // 3) out = ah @ (w_proj hi+lo) + b_proj (fp32)
    tc_gemm<<<dim3(CC / 128, MROWS / 128), 256, GEMM_SMEM>>>(
        CC, ah, wph, wpl, b_proj, out, nullptr, nullptr, 0);
}

// round 9
// speedup vs baseline: 8.7313x; 1.2995x over previous
#include <cuda_runtime.h>
#include <cuda_fp16.h>
#include <cstdint>
#include <math.h>

// Problem constants
#define BB 4
#define TT 2048
#define CC 1024
#define NH 16
#define HSZ 64
#define MROWS (BB*TT)        // 8192
#define THREECC (3*CC)       // 3072
#define KD 1024

// ---------------------------------------------------------------------------
// Global scratch (device globals: allocation-free). fp16 planes.
// ---------------------------------------------------------------------------
__device__ __half g_qkvh[(size_t)MROWS * THREECC];  // qkv hi plane (only plane)
__device__ __half g_xh[(size_t)MROWS * CC];         // x hi plane [M][K]
__device__ __half g_wah[(size_t)THREECC * CC];      // w_attn^T hi [N][K]
__device__ __half g_wal[(size_t)THREECC * CC];      // w_attn^T lo
__device__ __half g_wph[(size_t)CC * CC];           // w_proj^T hi [N][K]
__device__ __half g_wpl[(size_t)CC * CC];           // w_proj^T lo
__device__ __half g_ah[(size_t)MROWS * CC];         // attn out hi plane

// ---------------------------------------------------------------------------
// Helpers (compute_103-safe PTX: cp.async / ldmatrix / mma.sync)
// ---------------------------------------------------------------------------
__device__ __forceinline__ uint32_t smem_u32(const void* p) {
    uint32_t a;
    asm("{ .reg .u64 t; cvta.to.shared.u64 t, %1; cvt.u32.u64 %0, t; }"
        : "=r"(a) : "l"(p));
    return a;
}

__device__ __forceinline__ void cp16(uint32_t dst, const void* src) {
    asm volatile("cp.async.cg.shared.global [%0], [%1], 16;"
                 :: "r"(dst), "l"(src));
}
#define CP_COMMIT() asm volatile("cp.async.commit_group;" ::: "memory")
#define CP_WAIT(n)  asm volatile("cp.async.wait_group %0;" :: "n"(n) : "memory")

__device__ __forceinline__ void ldm_x4(uint32_t* r, uint32_t addr) {
    asm volatile("ldmatrix.sync.aligned.m8n8.x4.shared.b16 {%0,%1,%2,%3}, [%4];"
                 : "=r"(r[0]), "=r"(r[1]), "=r"(r[2]), "=r"(r[3]) : "r"(addr));
}
__device__ __forceinline__ void ldm_x4t(uint32_t* r, uint32_t addr) {
    asm volatile("ldmatrix.sync.aligned.m8n8.x4.trans.shared.b16 {%0,%1,%2,%3}, [%4];"
                 : "=r"(r[0]), "=r"(r[1]), "=r"(r[2]), "=r"(r[3]) : "r"(addr));
}

#define MMA_F16(acc, a, b0, b1)                                               \
    asm volatile(                                                             \
        "mma.sync.aligned.m16n8k16.row.col.f32.f16.f16.f32 "                  \
        "{%0,%1,%2,%3},{%4,%5,%6,%7},{%8,%9},{%0,%1,%2,%3};"                  \
        : "+f"((acc)[0]), "+f"((acc)[1]), "+f"((acc)[2]), "+f"((acc)[3])      \
        : "r"((a)[0]), "r"((a)[1]), "r"((a)[2]), "r"((a)[3]),                 \
          "r"(b0), "r"(b1))

__device__ __forceinline__ float ex2f(float x) {
    float y;
    asm("ex2.approx.f32 %0, %1;" : "=f"(y) : "f"(x));
    return y;
}

__device__ __forceinline__ uint32_t ex2_h2(uint32_t x) {
    uint32_t y;
    asm("ex2.approx.f16x2 %0, %1;" : "=r"(y) : "r"(x));
    return y;
}

__device__ __forceinline__ void split2h(float x, uint16_t& h, uint16_t& l) {
    __half hb = __float2half_rn(x);
    __half lb = __float2half_rn(x - __half2float(hb));
    h = *(uint16_t*)&hb;
    l = *(uint16_t*)&lb;
}

__device__ __forceinline__ uint32_t pack_h2(float a, float b) {
    __half2 p = __floats2half2_rn(a, b);
    return *(uint32_t*)&p;
}

// ---------------------------------------------------------------------------
// fp32 -> fp16 (hi only) cvt
// ---------------------------------------------------------------------------
__global__ __launch_bounds__(256) void k_cvt(
    const float4* __restrict__ s, uint2* __restrict__ h, int n4)
{
    const int i = blockIdx.x * 256 + threadIdx.x;
    if (i >= n4) return;
    const float4 v = s[i];
    h[i] = make_uint2(pack_h2(v.x, v.y), pack_h2(v.z, v.w));
}

// fp32 [K][N] -> fp16 hi/lo planes transposed [N][K]
__global__ __launch_bounds__(256) void k_splitT(
    const float* __restrict__ s, __half* __restrict__ h,
    __half* __restrict__ l, int K, int N)
{
    __shared__ float t[32][33];
    const int n0 = blockIdx.x * 32, k0 = blockIdx.y * 32;
    const int tx = threadIdx.x, ty = threadIdx.y;
    #pragma unroll
    for (int j = ty; j < 32; j += 8)
        t[j][tx] = s[(size_t)(k0 + j) * N + n0 + tx];
    __syncthreads();
    #pragma unroll
    for (int j = ty; j < 32; j += 8) {
        const float v = t[tx][j];
        uint16_t hh, ll;
        split2h(v, hh, ll);
        const size_t o = (size_t)(n0 + j) * K + k0 + tx;
        h[o] = *(__half*)&hh;
        l[o] = *(__half*)&ll;
    }
}

// ---------------------------------------------------------------------------
// Tensor-core GEMM: C = Ah[M][K] @ (Bh [+Bl])[N][K]^T + bias
// Bl term is skipped for output columns < loSkipN (Q columns of GEMM1:
// their error is RSS-masked by the downstream fp16 cvt).
// 128x128 CTA tile, BK=64, 256 thr, warp tile 64x32, 2-stage, 2 CTAs/SM.
// ---------------------------------------------------------------------------
#define STAGE_BYTES (3 * 18432)   // 55296
#define OFF_A  0
#define OFF_BH 18432
#define OFF_BL 36864
#define GEMM_SMEM (2 * STAGE_BYTES)   // 110592

__global__ __launch_bounds__(256, 2) void tc_gemm(
    int Ndim, int loSkipN,
    const __half* __restrict__ Ah,
    const __half* __restrict__ Bh, const __half* __restrict__ Bl,
    const float* __restrict__ bias, float* __restrict__ Cf,
    __half* __restrict__ Ch, int planes)
{
    extern __shared__ __align__(128) unsigned char smraw[];
    const uint32_t sb0 = smem_u32(smraw);
    const int tid = threadIdx.x, lane = tid & 31, wid = tid >> 5;
    const int m0 = blockIdx.y * 128, n0 = blockIdx.x * 128;
    const int wm = (wid >> 2) * 64, wn = (wid & 3) * 32;
    const bool useLo = (n0 >= loSkipN);

    const __half* gA  = Ah + (size_t)m0 * KD;
    const __half* gBh = Bh + (size_t)n0 * KD;
    const __half* gBl = Bl + (size_t)n0 * KD;

    auto issue = [&](int stage, int kc) {
        const int k0 = kc * 64;
        const uint32_t sb = sb0 + stage * STAGE_BYTES;
        #pragma unroll
        for (int j = 0; j < 4; j++) {
            const int c = j * 256 + tid;
            const int row = c >> 3, ch = c & 7;
            const uint32_t d = (uint32_t)(row * 144 + ch * 16);
            const size_t g = (size_t)row * KD + k0 + ch * 8;
            cp16(sb + OFF_A  + d, gA  + g);
            cp16(sb + OFF_BH + d, gBh + g);
            if (useLo) cp16(sb + OFF_BL + d, gBl + g);
        }
    };

    issue(0, 0); CP_COMMIT();
    issue(1, 1); CP_COMMIT();

    float acc[4][4][4] = {};

    const uint32_t aRowOff  = (uint32_t)((wm + (lane & 15)) * 144);
    const uint32_t aColHalf = (uint32_t)((lane >> 4) * 16);
    const uint32_t bRowOff  = (uint32_t)((wn + (lane >> 4) * 8 + (lane & 7)) * 144);
    const uint32_t bColHalf = (uint32_t)(((lane >> 3) & 1) * 16);

    for (int c = 0; c < 16; c++) {
        CP_WAIT(1);
        __syncthreads();

        const uint32_t sb = sb0 + (c & 1) * STAGE_BYTES;
        #pragma unroll
        for (int ks = 0; ks < 4; ks++) {
            uint32_t ah[4][4], bh[2][4], bl[2][4];
            const uint32_t acol = (uint32_t)(ks * 32) + aColHalf;
            const uint32_t bcol = (uint32_t)(ks * 32) + bColHalf;
            #pragma unroll
            for (int mt = 0; mt < 4; mt++)
                ldm_x4(ah[mt], sb + OFF_A + aRowOff + (uint32_t)(mt * 16 * 144) + acol);
            #pragma unroll
            for (int p = 0; p < 2; p++)
                ldm_x4(bh[p], sb + OFF_BH + bRowOff + (uint32_t)(p * 16 * 144) + bcol);
            if (useLo) {
                #pragma unroll
                for (int p = 0; p < 2; p++)
                    ldm_x4(bl[p], sb + OFF_BL + bRowOff + (uint32_t)(p * 16 * 144) + bcol);
            }
            #pragma unroll
            for (int mt = 0; mt < 4; mt++)
                #pragma unroll
                for (int nt = 0; nt < 4; nt++) {
                    const uint32_t* bp = &bh[nt >> 1][(nt & 1) * 2];
                    MMA_F16(acc[mt][nt], ah[mt], bp[0], bp[1]);   // Ah*Bh
                }
            if (useLo) {
                #pragma unroll
                for (int mt = 0; mt < 4; mt++)
                    #pragma unroll
                    for (int nt = 0; nt < 4; nt++) {
                        const uint32_t* bp = &bl[nt >> 1][(nt & 1) * 2];
                        MMA_F16(acc[mt][nt], ah[mt], bp[0], bp[1]);   // Ah*Bl
                    }
            }
        }
        __syncthreads();
        if (c + 2 < 16) issue(c & 1, c + 2);
        CP_COMMIT();
    }

    const int er = m0 + wm + (lane >> 2);
    const int ec = n0 + wn + (lane & 3) * 2;
    #pragma unroll
    for (int mt = 0; mt < 4; mt++) {
        #pragma unroll
        for (int nt = 0; nt < 4; nt++) {
            const int r = er + mt * 16;
            const int cn = ec + nt * 8;
            const float b0 = bias[cn], b1 = bias[cn + 1];
            const float v0 = acc[mt][nt][0] + b0, v1 = acc[mt][nt][1] + b1;
            const float v2 = acc[mt][nt][2] + b0, v3 = acc[mt][nt][3] + b1;
            if (!planes) {
                *(float2*)(Cf + (size_t)r * Ndim + cn) = make_float2(v0, v1);
                *(float2*)(Cf + (size_t)(r + 8) * Ndim + cn) = make_float2(v2, v3);
            } else {
                *(uint32_t*)(Ch + (size_t)r * Ndim + cn)       = pack_h2(v0, v1);
                *(uint32_t*)(Ch + (size_t)(r + 8) * Ndim + cn) = pack_h2(v2, v3);
            }
        }
    }
}

// ---------------------------------------------------------------------------
// fp16 causal flash attention, hi-planes only (K,V single plane).
// CTA = 128 threads (4 warps) x 64 queries. Stage = Kh+Vh = 18432B;
// 2 stages = 36864B => 4 CTAs/SM. exp via ex2.f16x2; row-sum via ones-MMA.
// ---------------------------------------------------------------------------
#define FLASH_SMEM (2 * 18432)

__global__ __launch_bounds__(128, 4) void flash_tc()
{
    extern __shared__ __align__(128) unsigned char fsm[];
    const uint32_t OKV = smem_u32(fsm);
    const int tid = threadIdx.x, lane = tid & 31, wid = tid >> 5;
    const int qt = (int)(gridDim.x - 1 - blockIdx.x);   // heavy CTAs first
    const int b = blockIdx.y >> 4, h = blockIdx.y & 15;
    const int q0 = qt * 64, wm = wid * 16;
    const size_t rowB = (size_t)b * TT;
    const int h64 = h * 64;
    const int NT = qt + 1;

    auto issueQ = [&]() {   // Q hi: 64 rows x 8 chunks -> buffer 0
        #pragma unroll
        for (int j = 0; j < 4; j++) {
            const int c = j * 128 + tid;
            const int row = c >> 3, ch = c & 7;
            const __half* src = g_qkvh + (rowB + q0 + row) * THREECC + h64 + ch * 8;
            cp16(OKV + row * 144 + ch * 16, src);
        }
    };
    auto issueKV = [&](int st, int tt) {   // Kh, Vh planes
        const int j0 = tt * 64;
        const uint32_t sb = OKV + st * 18432;
        #pragma unroll
        for (int j = 0; j < 8; j++) {
            const int c = j * 128 + tid;
            const int pl = c >> 9, row = (c >> 3) & 63, ch = c & 7;
            const __half* src = g_qkvh
                + (rowB + j0 + row) * THREECC + (pl ? 2 * CC : CC) + h64 + ch * 8;
            cp16(sb + pl * 9216 + row * 144 + ch * 16, src);
        }
    };

    const uint32_t koff = (uint32_t)(((((lane >> 4) & 1) * 8 + (lane & 7)) * 144)
                                     + ((lane >> 3) & 1) * 16);
    const uint32_t voff = (uint32_t)(((((lane >> 3) & 1) * 8 + (lane & 7)) * 144)
                                     + ((lane >> 4) & 1) * 16);
    const uint32_t qoff = (uint32_t)(((wm + ((lane >> 3) & 1) * 8 + (lane & 7)) * 144)
                                     + ((lane >> 4) & 1) * 16);

    issueQ(); CP_COMMIT();
    CP_WAIT(0);
    __syncthreads();
    uint32_t qhf[4][4];
    #pragma unroll
    for (int ks = 0; ks < 4; ks++)
        ldm_x4(qhf[ks], OKV + qoff + ks * 32);
    __syncthreads();

    issueKV(0, 0); CP_COMMIT();
    if (NT > 1) issueKV(1, 1);
    CP_COMMIT();

    float m0r = -1e30f, m1r = -1e30f, l0r = 0.f, l1r = 0.f;
    float o[8][4] = {};
    const float SC = 0.125f * 1.4426950408889634f;
    const int rq0 = q0 + wm + (lane >> 2);
    const int colb = (lane & 3) * 2;
    const uint32_t ONE2 = 0x3C003C00u;   // half2(1,1)

    for (int t = 0; t < NT; t++) {
        CP_WAIT(1);
        __syncthreads();
        const uint32_t sb = OKV + (t & 1) * 18432;
        const uint32_t KH = sb, VH = sb + 9216;
        const int j0 = t * 64;

        // ---- S = Qh.Kh^T
        float s[8][4] = {};
        #pragma unroll
        for (int ks = 0; ks < 4; ks++) {
            uint32_t kh[4][4];
            #pragma unroll
            for (int g = 0; g < 4; g++)
                ldm_x4(kh[g], KH + g * 2304 + ks * 32 + koff);
            #pragma unroll
            for (int g = 0; g < 4; g++) {
                MMA_F16(s[2*g],   qhf[ks], kh[g][0], kh[g][1]);
                MMA_F16(s[2*g+1], qhf[ks], kh[g][2], kh[g][3]);
            }
        }

        // ---- scale (+ causal mask on diagonal tile)
        if (t == qt) {
            #pragma unroll
            for (int nt = 0; nt < 8; nt++) {
                const int c0 = j0 + nt * 8 + colb;
                #pragma unroll
                for (int j = 0; j < 4; j++) {
                    const int cg = c0 + (j & 1);
                    const int rg = rq0 + ((j >> 1) << 3);
                    s[nt][j] = (cg <= rg) ? s[nt][j] * SC : -1e30f;
                }
            }
        } else {
            #pragma unroll
            for (int nt = 0; nt < 8; nt++)
                #pragma unroll
                for (int j = 0; j < 4; j++) s[nt][j] *= SC;
        }

        // ---- row max + running-max update
        float mx0 = -1e30f, mx1 = -1e30f;
        #pragma unroll
        for (int nt = 0; nt < 8; nt++) {
            mx0 = fmaxf(mx0, fmaxf(s[nt][0], s[nt][1]));
            mx1 = fmaxf(mx1, fmaxf(s[nt][2], s[nt][3]));
        }
        mx0 = fmaxf(mx0, __shfl_xor_sync(0xffffffffu, mx0, 1));
        mx0 = fmaxf(mx0, __shfl_xor_sync(0xffffffffu, mx0, 2));
        mx1 = fmaxf(mx1, __shfl_xor_sync(0xffffffffu, mx1, 1));
        mx1 = fmaxf(mx1, __shfl_xor_sync(0xffffffffu, mx1, 2));
        const float mn0 = fmaxf(m0r, mx0), mn1 = fmaxf(m1r, mx1);
        const float a0 = ex2f(m0r - mn0), a1 = ex2f(m1r - mn1);
        m0r = mn0; m1r = mn1;

        // ---- P = exp2(s - mn) directly in fp16; masked -> -inf -> 0
        uint32_t ph[4][4];
        #pragma unroll
        for (int kt = 0; kt < 4; kt++) {
            ph[kt][0] = ex2_h2(pack_h2(s[2*kt][0]   - mn0, s[2*kt][1]   - mn0));
            ph[kt][1] = ex2_h2(pack_h2(s[2*kt][2]   - mn1, s[2*kt][3]   - mn1));
            ph[kt][2] = ex2_h2(pack_h2(s[2*kt+1][0] - mn0, s[2*kt+1][1] - mn0));
            ph[kt][3] = ex2_h2(pack_h2(s[2*kt+1][2] - mn1, s[2*kt+1][3] - mn1));
        }

        // ---- row sums via ones-MMA
        float racc[4] = {0.f, 0.f, 0.f, 0.f};
        #pragma unroll
        for (int kt = 0; kt < 4; kt++)
            MMA_F16(racc, ph[kt], ONE2, ONE2);
        l0r = l0r * a0 + racc[0];
        l1r = l1r * a1 + racc[2];

        // ---- rescale O
        #pragma unroll
        for (int nt = 0; nt < 8; nt++) {
            o[nt][0] *= a0; o[nt][1] *= a0;
            o[nt][2] *= a1; o[nt][3] *= a1;
        }

        // ---- O += Ph.Vh
        #pragma unroll
        for (int kt = 0; kt < 4; kt++) {
            uint32_t vh[4][4];
            #pragma unroll
            for (int g = 0; g < 4; g++)
                ldm_x4t(vh[g], VH + kt * 2304 + g * 32 + voff);
            #pragma unroll
            for (int g = 0; g < 4; g++) {
                MMA_F16(o[2*g],   ph[kt], vh[g][0], vh[g][1]);
                MMA_F16(o[2*g+1], ph[kt], vh[g][2], vh[g][3]);
            }
        }

        __syncthreads();
        if (t + 2 < NT) issueKV(t & 1, t + 2);
        CP_COMMIT();
    }

    // ---- epilogue: normalize, cvt, store hi plane
    const float i0 = 1.0f / l0r, i1 = 1.0f / l1r;
    const size_t r0 = rowB + (size_t)rq0;
    #pragma unroll
    for (int nt = 0; nt < 8; nt++) {
        const int col = h64 + nt * 8 + colb;
        *(uint32_t*)(g_ah + r0 * CC + col)       = pack_h2(o[nt][0] * i0, o[nt][1] * i0);
        *(uint32_t*)(g_ah + (r0 + 8) * CC + col) = pack_h2(o[nt][2] * i1, o[nt][3] * i1);
    }
}

// ---------------------------------------------------------------------------
extern "C" void kernel_launch(void* const* d_in, const int* in_sizes, int n_in,
                              void* d_out, int out_size)
{
    const float* x      = (const float*)d_in[0];
    const float* w_attn = (const float*)d_in[1];
    const float* b_attn = (const float*)d_in[2];
    const float* w_proj = (const float*)d_in[3];
    const float* b_proj = (const float*)d_in[4];
    float* out = (float*)d_out;

    __half *qkvh, *xh, *wah, *wal, *wph, *wpl, *ah;
    cudaGetSymbolAddress((void**)&qkvh, g_qkvh);
    cudaGetSymbolAddress((void**)&xh, g_xh);
    cudaGetSymbolAddress((void**)&wah, g_wah);
    cudaGetSymbolAddress((void**)&wal, g_wal);
    cudaGetSymbolAddress((void**)&wph, g_wph);
    cudaGetSymbolAddress((void**)&wpl, g_wpl);
    cudaGetSymbolAddress((void**)&ah, g_ah);

    cudaFuncSetAttribute(tc_gemm,
                         cudaFuncAttributeMaxDynamicSharedMemorySize, GEMM_SMEM);
    cudaFuncSetAttribute(flash_tc,
                         cudaFuncAttributeMaxDynamicSharedMemorySize, FLASH_SMEM);

    // 0) input conversions
    {
        const int n4x = MROWS * CC / 4;
        k_cvt<<<(n4x + 255) / 256, 256>>>((const float4*)x, (uint2*)xh, n4x);
        k_splitT<<<dim3(THREECC / 32, CC / 32), dim3(32, 8)>>>(w_attn, wah, wal, CC, THREECC);
        k_splitT<<<dim3(CC / 32, CC / 32), dim3(32, 8)>>>(w_proj, wph, wpl, CC, CC);
    }

    // 1) qkv hi = fp16(xh @ (w_attn hi [+lo]) + b_attn); Q cols single-term
    tc_gemm<<<dim3(THREECC / 128, MROWS / 128), 256, GEMM_SMEM>>>(
        THREECC, CC, xh, wah, wal, b_attn, nullptr, qkvh, 1);

    // 2) fp16 causal flash attention (hi planes) -> g_ah
    flash_tc<<<dim3(TT / 64, BB * NH), 128, FLASH_SMEM>>>();

    // 3) out = ah @ (w_proj hi+lo) + b_proj (fp32)
    tc_gemm<<<dim3(CC / 128, MROWS / 128), 256, GEMM_SMEM>>>(
        CC, 0, ah, wph, wpl, b_proj, out, nullptr, 0);
}

// round 10
// speedup vs baseline: 11.6825x; 1.3380x over previous
#include <cuda_runtime.h>
#include <cuda_fp16.h>
#include <cstdint>
#include <math.h>

// Problem constants
#define BB 4
#define TT 2048
#define CC 1024
#define NH 16
#define HSZ 64
#define MROWS (BB*TT)        // 8192
#define THREECC (3*CC)       // 3072
#define KD 1024

// ---------------------------------------------------------------------------
// Global scratch (device globals: allocation-free). fp16 hi planes only.
// ---------------------------------------------------------------------------
__device__ __half g_qkvh[(size_t)MROWS * THREECC];  // qkv
__device__ __half g_xh[(size_t)MROWS * CC];         // x [M][K]
__device__ __half g_wah[(size_t)THREECC * CC];      // w_attn^T [N][K]
__device__ __half g_wph[(size_t)CC * CC];           // w_proj^T [N][K]
__device__ __half g_ah[(size_t)MROWS * CC];         // attn out

// ---------------------------------------------------------------------------
// Helpers (compute_103-safe PTX: cp.async / ldmatrix / mma.sync)
// ---------------------------------------------------------------------------
__device__ __forceinline__ uint32_t smem_u32(const void* p) {
    uint32_t a;
    asm("{ .reg .u64 t; cvta.to.shared.u64 t, %1; cvt.u32.u64 %0, t; }"
        : "=r"(a) : "l"(p));
    return a;
}

__device__ __forceinline__ void cp16(uint32_t dst, const void* src) {
    asm volatile("cp.async.cg.shared.global [%0], [%1], 16;"
                 :: "r"(dst), "l"(src));
}
#define CP_COMMIT() asm volatile("cp.async.commit_group;" ::: "memory")
#define CP_WAIT(n)  asm volatile("cp.async.wait_group %0;" :: "n"(n) : "memory")

__device__ __forceinline__ void ldm_x4(uint32_t* r, uint32_t addr) {
    asm volatile("ldmatrix.sync.aligned.m8n8.x4.shared.b16 {%0,%1,%2,%3}, [%4];"
                 : "=r"(r[0]), "=r"(r[1]), "=r"(r[2]), "=r"(r[3]) : "r"(addr));
}
__device__ __forceinline__ void ldm_x4t(uint32_t* r, uint32_t addr) {
    asm volatile("ldmatrix.sync.aligned.m8n8.x4.trans.shared.b16 {%0,%1,%2,%3}, [%4];"
                 : "=r"(r[0]), "=r"(r[1]), "=r"(r[2]), "=r"(r[3]) : "r"(addr));
}

#define MMA_F16(acc, a, b0, b1)                                               \
    asm volatile(                                                             \
        "mma.sync.aligned.m16n8k16.row.col.f32.f16.f16.f32 "                  \
        "{%0,%1,%2,%3},{%4,%5,%6,%7},{%8,%9},{%0,%1,%2,%3};"                  \
        : "+f"((acc)[0]), "+f"((acc)[1]), "+f"((acc)[2]), "+f"((acc)[3])      \
        : "r"((a)[0]), "r"((a)[1]), "r"((a)[2]), "r"((a)[3]),                 \
          "r"(b0), "r"(b1))

__device__ __forceinline__ float ex2f(float x) {
    float y;
    asm("ex2.approx.f32 %0, %1;" : "=f"(y) : "f"(x));
    return y;
}

__device__ __forceinline__ uint32_t ex2_h2(uint32_t x) {
    uint32_t y;
    asm("ex2.approx.f16x2 %0, %1;" : "=r"(y) : "r"(x));
    return y;
}

__device__ __forceinline__ uint32_t pack_h2(float a, float b) {
    __half2 p = __floats2half2_rn(a, b);
    return *(uint32_t*)&p;
}

// ---------------------------------------------------------------------------
// fp32 -> fp16 cvt (flat)
// ---------------------------------------------------------------------------
__global__ __launch_bounds__(256) void k_cvt(
    const float4* __restrict__ s, uint2* __restrict__ h, int n4)
{
    const int i = blockIdx.x * 256 + threadIdx.x;
    if (i >= n4) return;
    const float4 v = s[i];
    h[i] = make_uint2(pack_h2(v.x, v.y), pack_h2(v.z, v.w));
}

// fp32 [K][N] -> fp16 transposed [N][K]
__global__ __launch_bounds__(256) void k_cvtT(
    const float* __restrict__ s, __half* __restrict__ h, int K, int N)
{
    __shared__ float t[32][33];
    const int n0 = blockIdx.x * 32, k0 = blockIdx.y * 32;
    const int tx = threadIdx.x, ty = threadIdx.y;
    #pragma unroll
    for (int j = ty; j < 32; j += 8)
        t[j][tx] = s[(size_t)(k0 + j) * N + n0 + tx];
    __syncthreads();
    #pragma unroll
    for (int j = ty; j < 32; j += 8)
        h[(size_t)(n0 + j) * K + k0 + tx] = __float2half_rn(t[tx][j]);
}

// ---------------------------------------------------------------------------
// fp16 tensor-core GEMM: C = A[M][K] @ Bt[N][K]^T + bias
// 128x128 CTA tile, BK=64, 256 thr, warp tile 64x32, 2-stage, 2 CTAs/SM.
// Fragment-level software pipeline: LDSM for slice ks+1 issued before the
// 16 MMAs of slice ks (double-buffered fragments).
// ---------------------------------------------------------------------------
#define STAGE_BYTES (2 * 18432)   // 36864
#define OFF_A  0
#define OFF_B  18432
#define GEMM_SMEM (2 * STAGE_BYTES)   // 73728

__global__ __launch_bounds__(256, 2) void tc_gemm(
    int Ndim,
    const __half* __restrict__ Ah, const __half* __restrict__ Bh,
    const float* __restrict__ bias, float* __restrict__ Cf,
    __half* __restrict__ Ch, int planes)
{
    extern __shared__ __align__(128) unsigned char smraw[];
    const uint32_t sb0 = smem_u32(smraw);
    const int tid = threadIdx.x, lane = tid & 31, wid = tid >> 5;
    const int m0 = blockIdx.y * 128, n0 = blockIdx.x * 128;
    const int wm = (wid >> 2) * 64, wn = (wid & 3) * 32;

    const __half* gA = Ah + (size_t)m0 * KD;
    const __half* gB = Bh + (size_t)n0 * KD;

    auto issue = [&](int stage, int kc) {
        const int k0 = kc * 64;
        const uint32_t sb = sb0 + stage * STAGE_BYTES;
        #pragma unroll
        for (int j = 0; j < 4; j++) {
            const int c = j * 256 + tid;
            const int row = c >> 3, ch = c & 7;
            const uint32_t d = (uint32_t)(row * 144 + ch * 16);
            const size_t g = (size_t)row * KD + k0 + ch * 8;
            cp16(sb + OFF_A + d, gA + g);
            cp16(sb + OFF_B + d, gB + g);
        }
    };

    issue(0, 0); CP_COMMIT();
    issue(1, 1); CP_COMMIT();

    float acc[4][4][4] = {};

    const uint32_t aRowOff  = (uint32_t)((wm + (lane & 15)) * 144);
    const uint32_t aColHalf = (uint32_t)((lane >> 4) * 16);
    const uint32_t bRowOff  = (uint32_t)((wn + (lane >> 4) * 8 + (lane & 7)) * 144);
    const uint32_t bColHalf = (uint32_t)(((lane >> 3) & 1) * 16);

    uint32_t af[2][4][4], bf[2][2][4];

    for (int c = 0; c < 16; c++) {
        CP_WAIT(1);
        __syncthreads();

        const uint32_t sb = sb0 + (c & 1) * STAGE_BYTES;
        // preload slice 0 fragments
        #pragma unroll
        for (int mt = 0; mt < 4; mt++)
            ldm_x4(af[0][mt], sb + OFF_A + aRowOff + (uint32_t)(mt * 16 * 144) + aColHalf);
        #pragma unroll
        for (int p = 0; p < 2; p++)
            ldm_x4(bf[0][p], sb + OFF_B + bRowOff + (uint32_t)(p * 16 * 144) + bColHalf);

        #pragma unroll
        for (int ks = 0; ks < 4; ks++) {
            const int cur = ks & 1, nxt = cur ^ 1;
            if (ks < 3) {   // prefetch next slice fragments ahead of MMAs
                const uint32_t acol = (uint32_t)((ks + 1) * 32) + aColHalf;
                const uint32_t bcol = (uint32_t)((ks + 1) * 32) + bColHalf;
                #pragma unroll
                for (int mt = 0; mt < 4; mt++)
                    ldm_x4(af[nxt][mt], sb + OFF_A + aRowOff + (uint32_t)(mt * 16 * 144) + acol);
                #pragma unroll
                for (int p = 0; p < 2; p++)
                    ldm_x4(bf[nxt][p], sb + OFF_B + bRowOff + (uint32_t)(p * 16 * 144) + bcol);
            }
            #pragma unroll
            for (int mt = 0; mt < 4; mt++)
                #pragma unroll
                for (int nt = 0; nt < 4; nt++) {
                    const uint32_t* bp = &bf[cur][nt >> 1][(nt & 1) * 2];
                    MMA_F16(acc[mt][nt], af[cur][mt], bp[0], bp[1]);
                }
        }
        __syncthreads();
        if (c + 2 < 16) issue(c & 1, c + 2);
        CP_COMMIT();
    }

    const int er = m0 + wm + (lane >> 2);
    const int ec = n0 + wn + (lane & 3) * 2;
    #pragma unroll
    for (int mt = 0; mt < 4; mt++) {
        #pragma unroll
        for (int nt = 0; nt < 4; nt++) {
            const int r = er + mt * 16;
            const int cn = ec + nt * 8;
            const float b0 = bias[cn], b1 = bias[cn + 1];
            const float v0 = acc[mt][nt][0] + b0, v1 = acc[mt][nt][1] + b1;
            const float v2 = acc[mt][nt][2] + b0, v3 = acc[mt][nt][3] + b1;
            if (!planes) {
                *(float2*)(Cf + (size_t)r * Ndim + cn) = make_float2(v0, v1);
                *(float2*)(Cf + (size_t)(r + 8) * Ndim + cn) = make_float2(v2, v3);
            } else {
                *(uint32_t*)(Ch + (size_t)r * Ndim + cn)       = pack_h2(v0, v1);
                *(uint32_t*)(Ch + (size_t)(r + 8) * Ndim + cn) = pack_h2(v2, v3);
            }
        }
    }
}

// ---------------------------------------------------------------------------
// fp16 causal flash attention (hi planes; unchanged from R9).
// CTA = 128 threads x 64 queries; 4 CTAs/SM.
// ---------------------------------------------------------------------------
#define FLASH_SMEM (2 * 18432)

__global__ __launch_bounds__(128, 4) void flash_tc()
{
    extern __shared__ __align__(128) unsigned char fsm[];
    const uint32_t OKV = smem_u32(fsm);
    const int tid = threadIdx.x, lane = tid & 31, wid = tid >> 5;
    const int qt = (int)(gridDim.x - 1 - blockIdx.x);   // heavy CTAs first
    const int b = blockIdx.y >> 4, h = blockIdx.y & 15;
    const int q0 = qt * 64, wm = wid * 16;
    const size_t rowB = (size_t)b * TT;
    const int h64 = h * 64;
    const int NT = qt + 1;

    auto issueQ = [&]() {
        #pragma unroll
        for (int j = 0; j < 4; j++) {
            const int c = j * 128 + tid;
            const int row = c >> 3, ch = c & 7;
            const __half* src = g_qkvh + (rowB + q0 + row) * THREECC + h64 + ch * 8;
            cp16(OKV + row * 144 + ch * 16, src);
        }
    };
    auto issueKV = [&](int st, int tt) {
        const int j0 = tt * 64;
        const uint32_t sb = OKV + st * 18432;
        #pragma unroll
        for (int j = 0; j < 8; j++) {
            const int c = j * 128 + tid;
            const int pl = c >> 9, row = (c >> 3) & 63, ch = c & 7;
            const __half* src = g_qkvh
                + (rowB + j0 + row) * THREECC + (pl ? 2 * CC : CC) + h64 + ch * 8;
            cp16(sb + pl * 9216 + row * 144 + ch * 16, src);
        }
    };

    const uint32_t koff = (uint32_t)(((((lane >> 4) & 1) * 8 + (lane & 7)) * 144)
                                     + ((lane >> 3) & 1) * 16);
    const uint32_t voff = (uint32_t)(((((lane >> 3) & 1) * 8 + (lane & 7)) * 144)
                                     + ((lane >> 4) & 1) * 16);
    const uint32_t qoff = (uint32_t)(((wm + ((lane >> 3) & 1) * 8 + (lane & 7)) * 144)
                                     + ((lane >> 4) & 1) * 16);

    issueQ(); CP_COMMIT();
    CP_WAIT(0);
    __syncthreads();
    uint32_t qhf[4][4];
    #pragma unroll
    for (int ks = 0; ks < 4; ks++)
        ldm_x4(qhf[ks], OKV + qoff + ks * 32);
    __syncthreads();

    issueKV(0, 0); CP_COMMIT();
    if (NT > 1) issueKV(1, 1);
    CP_COMMIT();

    float m0r = -1e30f, m1r = -1e30f, l0r = 0.f, l1r = 0.f;
    float o[8][4] = {};
    const float SC = 0.125f * 1.4426950408889634f;
    const int rq0 = q0 + wm + (lane >> 2);
    const int colb = (lane & 3) * 2;
    const uint32_t ONE2 = 0x3C003C00u;

    for (int t = 0; t < NT; t++) {
        CP_WAIT(1);
        __syncthreads();
        const uint32_t sb = OKV + (t & 1) * 18432;
        const uint32_t KH = sb, VH = sb + 9216;
        const int j0 = t * 64;

        float s[8][4] = {};
        #pragma unroll
        for (int ks = 0; ks < 4; ks++) {
            uint32_t kh[4][4];
            #pragma unroll
            for (int g = 0; g < 4; g++)
                ldm_x4(kh[g], KH + g * 2304 + ks * 32 + koff);
            #pragma unroll
            for (int g = 0; g < 4; g++) {
                MMA_F16(s[2*g],   qhf[ks], kh[g][0], kh[g][1]);
                MMA_F16(s[2*g+1], qhf[ks], kh[g][2], kh[g][3]);
            }
        }

        if (t == qt) {
            #pragma unroll
            for (int nt = 0; nt < 8; nt++) {
                const int c0 = j0 + nt * 8 + colb;
                #pragma unroll
                for (int j = 0; j < 4; j++) {
                    const int cg = c0 + (j & 1);
                    const int rg = rq0 + ((j >> 1) << 3);
                    s[nt][j] = (cg <= rg) ? s[nt][j] * SC : -1e30f;
                }
            }
        } else {
            #pragma unroll
            for (int nt = 0; nt < 8; nt++)
                #pragma unroll
                for (int j = 0; j < 4; j++) s[nt][j] *= SC;
        }

        float mx0 = -1e30f, mx1 = -1e30f;
        #pragma unroll
        for (int nt = 0; nt < 8; nt++) {
            mx0 = fmaxf(mx0, fmaxf(s[nt][0], s[nt][1]));
            mx1 = fmaxf(mx1, fmaxf(s[nt][2], s[nt][3]));
        }
        mx0 = fmaxf(mx0, __shfl_xor_sync(0xffffffffu, mx0, 1));
        mx0 = fmaxf(mx0, __shfl_xor_sync(0xffffffffu, mx0, 2));
        mx1 = fmaxf(mx1, __shfl_xor_sync(0xffffffffu, mx1, 1));
        mx1 = fmaxf(mx1, __shfl_xor_sync(0xffffffffu, mx1, 2));
        const float mn0 = fmaxf(m0r, mx0), mn1 = fmaxf(m1r, mx1);
        const float a0 = ex2f(m0r - mn0), a1 = ex2f(m1r - mn1);
        m0r = mn0; m1r = mn1;

        uint32_t ph[4][4];
        #pragma unroll
        for (int kt = 0; kt < 4; kt++) {
            ph[kt][0] = ex2_h2(pack_h2(s[2*kt][0]   - mn0, s[2*kt][1]   - mn0));
            ph[kt][1] = ex2_h2(pack_h2(s[2*kt][2]   - mn1, s[2*kt][3]   - mn1));
            ph[kt][2] = ex2_h2(pack_h2(s[2*kt+1][0] - mn0, s[2*kt+1][1] - mn0));
            ph[kt][3] = ex2_h2(pack_h2(s[2*kt+1][2] - mn1, s[2*kt+1][3] - mn1));
        }

        float racc[4] = {0.f, 0.f, 0.f, 0.f};
        #pragma unroll
        for (int kt = 0; kt < 4; kt++)
            MMA_F16(racc, ph[kt], ONE2, ONE2);
        l0r = l0r * a0 + racc[0];
        l1r = l1r * a1 + racc[2];

        #pragma unroll
        for (int nt = 0; nt < 8; nt++) {
            o[nt][0] *= a0; o[nt][1] *= a0;
            o[nt][2] *= a1; o[nt][3] *= a1;
        }

        #pragma unroll
        for (int kt = 0; kt < 4; kt++) {
            uint32_t vh[4][4];
            #pragma unroll
            for (int g = 0; g < 4; g++)
                ldm_x4t(vh[g], VH + kt * 2304 + g * 32 + voff);
            #pragma unroll
            for (int g = 0; g < 4; g++) {
                MMA_F16(o[2*g],   ph[kt], vh[g][0], vh[g][1]);
                MMA_F16(o[2*g+1], ph[kt], vh[g][2], vh[g][3]);
            }
        }

        __syncthreads();
        if (t + 2 < NT) issueKV(t & 1, t + 2);
        CP_COMMIT();
    }

    const float i0 = 1.0f / l0r, i1 = 1.0f / l1r;
    const size_t r0 = rowB + (size_t)rq0;
    #pragma unroll
    for (int nt = 0; nt < 8; nt++) {
        const int col = h64 + nt * 8 + colb;
        *(uint32_t*)(g_ah + r0 * CC + col)       = pack_h2(o[nt][0] * i0, o[nt][1] * i0);
        *(uint32_t*)(g_ah + (r0 + 8) * CC + col) = pack_h2(o[nt][2] * i1, o[nt][3] * i1);
    }
}

// ---------------------------------------------------------------------------
extern "C" void kernel_launch(void* const* d_in, const int* in_sizes, int n_in,
                              void* d_out, int out_size)
{
    const float* x      = (const float*)d_in[0];
    const float* w_attn = (const float*)d_in[1];
    const float* b_attn = (const float*)d_in[2];
    const float* w_proj = (const float*)d_in[3];
    const float* b_proj = (const float*)d_in[4];
    float* out = (float*)d_out;

    __half *qkvh, *xh, *wah, *wph, *ah;
    cudaGetSymbolAddress((void**)&qkvh, g_qkvh);
    cudaGetSymbolAddress((void**)&xh, g_xh);
    cudaGetSymbolAddress((void**)&wah, g_wah);
    cudaGetSymbolAddress((void**)&wph, g_wph);
    cudaGetSymbolAddress((void**)&ah, g_ah);

    cudaFuncSetAttribute(tc_gemm,
                         cudaFuncAttributeMaxDynamicSharedMemorySize, GEMM_SMEM);
    cudaFuncSetAttribute(flash_tc,
                         cudaFuncAttributeMaxDynamicSharedMemorySize, FLASH_SMEM);

    // 0) input conversions (hi planes only)
    {
        const int n4x = MROWS * CC / 4;
        k_cvt<<<(n4x + 255) / 256, 256>>>((const float4*)x, (uint2*)xh, n4x);
        k_cvtT<<<dim3(THREECC / 32, CC / 32), dim3(32, 8)>>>(w_attn, wah, CC, THREECC);
        k_cvtT<<<dim3(CC / 32, CC / 32), dim3(32, 8)>>>(w_proj, wph, CC, CC);
    }

    // 1) qkv = fp16(xh @ w_attn^T + b_attn)
    tc_gemm<<<dim3(THREECC / 128, MROWS / 128), 256, GEMM_SMEM>>>(
        THREECC, xh, wah, b_attn, nullptr, qkvh, 1);

    // 2) fp16 causal flash attention -> g_ah
    flash_tc<<<dim3(TT / 64, BB * NH), 128, FLASH_SMEM>>>();

    // 3) out = ah @ w_proj^T + b_proj (fp32)
    tc_gemm<<<dim3(CC / 128, MROWS / 128), 256, GEMM_SMEM>>>(
        CC, ah, wph, b_proj, out, nullptr, 0);
}